// round 4
// baseline (speedup 1.0000x reference)
#include <cuda_runtime.h>
#include <cuda_bf16.h>
#include <mma.h>
#include <math.h>

using namespace nvcuda;

// Problem constants (fixed by the dataset)
#define NN   100000   // entities
#define DD   300      // e_hidden
#define EE   400000   // triples (KG1)
#define EA   800000   // symmetric all-edge count (2*EH)
#define RRR  2000     // relations
#define RH   100      // r_hidden
#define LG   60000    // line-graph edges

static const int TPB = 256;

// ---------------- device scratch (static globals; no allocation) -------------
__device__ float g_x   [(size_t)NN*DD];   // current entity features
__device__ float g_t   [(size_t)NN*DD];   // GEMM output (xw / gate pre-sigmoid)
__device__ float g_agg [(size_t)NN*DD];   // aggregation accumulator
__device__ float g_deg [NN];
__device__ float g_dinv[NN];
__device__ float g_enorm[EA];             // per-edge gcn norm (reused both layers)
__device__ float g_pA  [NN];              // per-node projections
__device__ float g_pB  [NN];
__device__ int   g_mx  [NN];              // segment max (encoded)
__device__ float g_sm  [NN];              // segment sum
__device__ float g_ew  [EA];              // per-edge scratch (scores -> p -> alpha)
__device__ float g_vi  [LG];
__device__ float g_vj  [LG];
__device__ float g_v2  [LG];
__device__ float g_al  [LG];
__device__ int   g_rmx [RRR];
__device__ float g_rsm [RRR];
__device__ float g_relA[RRR*RH];          // rel_merge
__device__ float g_relB[RRR*RH];          // rel_tri
__device__ float g_rgate[RRR*RH];
__device__ float g_xr  [RRR*RH];          // highway(rel_merge, rel_tri)
__device__ float g_projR2[2*RRR];         // (rel_emb @ a_r) for GAT
__device__ float g_projR3[RRR];           // (x_r @ g2e_ar)

// ---------------- helpers ----------------------------------------------------
__device__ __forceinline__ int encf(float f) {
    int i = __float_as_int(f);
    return i >= 0 ? i : (i ^ 0x7fffffff);
}
__device__ __forceinline__ float decf(int i) {
    return __int_as_float(i >= 0 ? i : (i ^ 0x7fffffff));
}
// 16B vector atomic add (sm_90+); all destinations proven 16B-aligned.
__device__ __forceinline__ void red4(float* p, float a, float b, float c, float d) {
    asm volatile("red.global.add.v4.f32 [%0], {%1, %2, %3, %4};"
                 :: "l"(p), "f"(a), "f"(b), "f"(c), "f"(d) : "memory");
}

// ---------------- elementwise / init -----------------------------------------
__global__ void k_zero(float* p, long long n) {
    long long i = blockIdx.x * (long long)blockDim.x + threadIdx.x;
    if (i < n) p[i] = 0.f;
}
__global__ void k_initseg(int* mx, float* sm, int n) {
    int i = blockIdx.x * blockDim.x + threadIdx.x;
    if (i < n) { mx[i] = 0x80000000; sm[i] = 0.f; }
}

// ---------------- degree / norm ----------------------------------------------
__global__ void k_deg(const int* __restrict__ dst, float* deg, int ne) {
    int e = blockIdx.x * blockDim.x + threadIdx.x;
    if (e < ne) atomicAdd(&deg[dst[e]], 1.f);
}
__global__ void k_dinv(const float* __restrict__ deg, float* dinv, int n) {
    int i = blockIdx.x * blockDim.x + threadIdx.x;
    if (i < n) { float d = deg[i]; dinv[i] = d > 0.f ? rsqrtf(d) : 0.f; }
}
__global__ void k_enorm(const int* __restrict__ js, const int* __restrict__ is,
                        const float* __restrict__ dinv, float* en, int ne) {
    int e = blockIdx.x * blockDim.x + threadIdx.x;
    if (e < ne) en[e] = dinv[js[e]] * dinv[is[e]];
}

// ------ GEMM (tensor core, split-bf16 3-MMA): Out[n,m] = X[n,K] @ W[m,K]^T ---
// A = Ah + Al, B = Bh + Bl (bf16 each); acc += Ah*Bh + Ah*Bl + Al*Bh in fp32.
// Dropped Al*Bl term is ~2^-16 relative -> ~1e-5 end-to-end error.
// 64x64 tile, 8 warps; warp w -> m-rows [16*(w%4)), n-cols [32*(w/4)).
__global__ __launch_bounds__(256) void k_gemm_tc(
        const float* __restrict__ X, const float* __restrict__ W,
        const float* __restrict__ bias, float* __restrict__ Out,
        int n, int K, int m) {
    __shared__ __nv_bfloat16 A2[64][32];   // cols 0..15 hi, 16..31 lo (ldm 32)
    __shared__ __nv_bfloat16 B2[64][32];
    __shared__ float stage[64 * 64];

    const int tid = threadIdx.x;
    const int wid = tid >> 5;
    const int wm = wid & 3;        // m sub-tile 0..3
    const int wn = wid >> 2;       // n half 0..1
    const int rb = blockIdx.y * 64, cb = blockIdx.x * 64;

    wmma::fragment<wmma::accumulator, 16, 16, 16, float> acc[2];
    wmma::fill_fragment(acc[0], 0.f);
    wmma::fill_fragment(acc[1], 0.f);

    const int r  = tid >> 2;         // 0..63 (tile row)
    const int c0 = (tid & 3) * 4;    // 0,4,8,12

    for (int k0 = 0; k0 < K; k0 += 16) {
#pragma unroll
        for (int q = 0; q < 4; q++) {
            int gc = k0 + c0 + q;
            bool kok = gc < K;
            float xv = (kok && rb + r < n) ? X[(size_t)(rb + r) * K + gc] : 0.f;
            __nv_bfloat16 xh = __float2bfloat16(xv);
            A2[r][c0 + q]      = xh;
            A2[r][16 + c0 + q] = __float2bfloat16(xv - __bfloat162float(xh));
            float wv = (kok && cb + r < m) ? W[(size_t)(cb + r) * K + gc] : 0.f;
            __nv_bfloat16 wh = __float2bfloat16(wv);
            B2[r][c0 + q]      = wh;
            B2[r][16 + c0 + q] = __float2bfloat16(wv - __bfloat162float(wv == 0.f ? 0.f : wv - 0.f));
            // NOTE: compute lo correctly below (overwrite) — kept simple & exact:
            B2[r][16 + c0 + q] = __float2bfloat16(wv - __bfloat162float(wh));
        }
        __syncthreads();

        wmma::fragment<wmma::matrix_a, 16, 16, 16, __nv_bfloat16, wmma::row_major> ah, al;
        wmma::load_matrix_sync(ah, &A2[16 * wm][0],  32);
        wmma::load_matrix_sync(al, &A2[16 * wm][16], 32);
#pragma unroll
        for (int t = 0; t < 2; t++) {
            wmma::fragment<wmma::matrix_b, 16, 16, 16, __nv_bfloat16, wmma::col_major> bh, bl;
            int nrow = 32 * wn + 16 * t;
            wmma::load_matrix_sync(bh, &B2[nrow][0],  32);
            wmma::load_matrix_sync(bl, &B2[nrow][16], 32);
            wmma::mma_sync(acc[t], ah, bh, acc[t]);
            wmma::mma_sync(acc[t], ah, bl, acc[t]);
            wmma::mma_sync(acc[t], al, bh, acc[t]);
        }
        __syncthreads();
    }

#pragma unroll
    for (int t = 0; t < 2; t++)
        wmma::store_matrix_sync(&stage[(16 * wm) * 64 + 32 * wn + 16 * t],
                                acc[t], 64, wmma::mem_row_major);
    __syncthreads();

    for (int e = tid; e < 64 * 64; e += 256) {
        int rr = e >> 6, cc = e & 63;
        int gr = rb + rr, gc = cb + cc;
        if (gr < n && gc < m) {
            float v = stage[e];
            if (bias) v += bias[gc];
            Out[(size_t)gr * m + gc] = v;
        }
    }
}

// ---- weighted scatter-add: out[dst[e], ofs:ofs+D] += w[e]*X[src[e],:D] ------
// D % 4 == 0 and all row bases 16B-aligned -> red.v4 (4x fewer L2 atomics).
__global__ void k_wagg(const int* __restrict__ srcIdx, const int* __restrict__ dstIdx,
                       const float* __restrict__ w, const float* __restrict__ X,
                       int ss, float* out, int os, int ofs, int D, int ne) {
    int e    = (int)((blockIdx.x * (long long)blockDim.x + threadIdx.x) >> 5);
    int lane = threadIdx.x & 31;
    if (e >= ne) return;
    float wt = w[e];
    const float4* src = reinterpret_cast<const float4*>(X + (size_t)srcIdx[e] * ss);
    float* dst = out + (size_t)dstIdx[e] * os + ofs;
    int D4 = D >> 2;
    for (int c = lane; c < D4; c += 32) {
        float4 v = src[c];
        red4(dst + c * 4, wt * v.x, wt * v.y, wt * v.z, wt * v.w);
    }
}

// ---------------- highway combine (float4): out = sig(gate)*x2' + (1-sig)*xin
__global__ void k_highway4(const float4* __restrict__ xin, const float4* __restrict__ x2,
                           const float4* __restrict__ gate, float4* out, long long n4, int relu2) {
    long long i = blockIdx.x * (long long)blockDim.x + threadIdx.x;
    if (i >= n4) return;
    float4 gv = gate[i], bv = x2[i], av = xin[i], o;
    float g;
    g = 1.f / (1.f + expf(-gv.x)); o.x = g * (relu2 ? fmaxf(bv.x, 0.f) : bv.x) + (1.f - g) * av.x;
    g = 1.f / (1.f + expf(-gv.y)); o.y = g * (relu2 ? fmaxf(bv.y, 0.f) : bv.y) + (1.f - g) * av.y;
    g = 1.f / (1.f + expf(-gv.z)); o.z = g * (relu2 ? fmaxf(bv.z, 0.f) : bv.z) + (1.f - g) * av.z;
    g = 1.f / (1.f + expf(-gv.w)); o.w = g * (relu2 ? fmaxf(bv.w, 0.f) : bv.w) + (1.f - g) * av.w;
    out[i] = o;
}

// ---------------- segment softmax primitives ---------------------------------
__global__ void k_maxval(const float* __restrict__ val, const int* __restrict__ seg,
                         int* mx, int ne) {
    int e = blockIdx.x * blockDim.x + threadIdx.x;
    if (e < ne) atomicMax(&mx[seg[e]], encf(val[e]));
}
__global__ void k_expval(const float* __restrict__ vin, float* pout,
                         const int* __restrict__ seg, const int* __restrict__ mx,
                         float* sm, int ne) {
    int e = blockIdx.x * blockDim.x + threadIdx.x;
    if (e >= ne) return;
    float p = expf(vin[e] - decf(mx[seg[e]]));
    pout[e] = p;
    atomicAdd(&sm[seg[e]], p);
}
__global__ void k_div(float* p, const int* __restrict__ seg,
                      const float* __restrict__ sm, int ne) {
    int e = blockIdx.x * blockDim.x + threadIdx.x;
    if (e < ne) p[e] = p[e] / (sm[seg[e]] + 1e-16f);
}
__global__ void k_add(const float* a, const float* b, float* o, int ne) {
    int e = blockIdx.x * blockDim.x + threadIdx.x;
    if (e < ne) o[e] = a[e] + b[e];
}

// GAT-style edge score: v = pa[ia] + pb[ib] (+ pc[ic]); leaky_relu; store + seg-max
__global__ void k_score(const float* __restrict__ pa, const int* __restrict__ ia,
                        const float* __restrict__ pb, const int* __restrict__ ib,
                        const float* __restrict__ pc, const int* __restrict__ ic,
                        const int* __restrict__ seg, float* out, int* mx, int ne) {
    int e = blockIdx.x * blockDim.x + threadIdx.x;
    if (e >= ne) return;
    float v = pa[ia[e]] + pb[ib[e]];
    if (pc) v += pc[ic[e]];
    v = v >= 0.f ? v : 0.01f * v;
    out[e] = v;
    atomicMax(&mx[seg[e]], encf(v));
}

// ---------------- relu / output prep -----------------------------------------
__global__ void k_relu(float* p, long long n) {
    long long i = blockIdx.x * (long long)blockDim.x + threadIdx.x;
    if (i < n) p[i] = fmaxf(p[i], 0.f);
}
// one pass over d_out: cols 0..299 <- x, cols 300..799 <- 0
__global__ void k_prep_out(float* out, const float* __restrict__ x) {
    long long i = blockIdx.x * (long long)blockDim.x + threadIdx.x;
    long long n = (long long)NN * 800;
    if (i >= n) return;
    int r = (int)(i / 800), c = (int)(i % 800);
    out[i] = (c < DD) ? x[(size_t)r * DD + c] : 0.f;
}
__global__ void k_relu_str(float* out, int rows, int rstride, int ofs, int D) {
    long long i = blockIdx.x * (long long)blockDim.x + threadIdx.x;
    long long n = (long long)rows * D;
    if (i >= n) return;
    int r = (int)(i / D), c = (int)(i % D);
    size_t p = (size_t)r * rstride + ofs + c;
    out[p] = fmaxf(out[p], 0.f);
}

// ---------------- per-row dot products (warp per row) ------------------------
__global__ void k_dot2(const float* __restrict__ X, int stride,
                       const float* __restrict__ a, const float* __restrict__ b,
                       float* outA, float* outB, int n, int D) {
    int w    = (int)((blockIdx.x * (long long)blockDim.x + threadIdx.x) >> 5);
    int lane = threadIdx.x & 31;
    if (w >= n) return;
    const float* row = X + (size_t)w * stride;
    float sa = 0.f, sb = 0.f;
    for (int c = lane; c < D; c += 32) {
        float x = row[c];
        sa += x * a[c];
        if (b) sb += x * b[c];
    }
#pragma unroll
    for (int o = 16; o; o >>= 1) {
        sa += __shfl_down_sync(0xffffffffu, sa, o);
        if (b) sb += __shfl_down_sync(0xffffffffu, sb, o);
    }
    if (lane == 0) { outA[w] = sa; if (b) outB[w] = sb; }
}

// proj over rel_emb = concat([rel_cat, rel_cat], axis=0), rel_cat = [merge|tri]
__global__ void k_projR2(const float* __restrict__ relA, const float* __restrict__ relB,
                         const float* __restrict__ ar, float* out) {
    int w    = (int)((blockIdx.x * (long long)blockDim.x + threadIdx.x) >> 5);
    int lane = threadIdx.x & 31;
    if (w >= 2 * RRR) return;
    int r = w < RRR ? w : w - RRR;
    float s = 0.f;
    for (int c = lane; c < RH; c += 32)
        s += relA[(size_t)r * RH + c] * ar[c] + relB[(size_t)r * RH + c] * ar[RH + c];
#pragma unroll
    for (int o = 16; o; o >>= 1) s += __shfl_down_sync(0xffffffffu, s, o);
    if (lane == 0) out[w] = s;
}

// ---------------- host orchestration -----------------------------------------
static inline int divup(long long a, int b) { return (int)((a + b - 1) / b); }

extern "C" void kernel_launch(void* const* d_in, const int* in_sizes, int n_in,
                              void* d_out, int out_size) {
    const float* x_e      = (const float*)d_in[0];
    const float* merge_v  = (const float*)d_in[1];
    const float* tri_v    = (const float*)d_in[2];
    const float* gcn1_w   = (const float*)d_in[3];
    const float* hw1_w    = (const float*)d_in[4];
    const float* hw1_b    = (const float*)d_in[5];
    const float* gcn2_w   = (const float*)d_in[6];
    const float* hw2_w    = (const float*)d_in[7];
    const float* hw2_b    = (const float*)d_in[8];
    const float* rel_out1 = (const float*)d_in[9];
    const float* rel_tri1 = (const float*)d_in[10];
    const float* hwr_w    = (const float*)d_in[11];
    const float* hwr_b    = (const float*)d_in[12];
    const float* gat_ai   = (const float*)d_in[13];
    const float* gat_aj   = (const float*)d_in[14];
    const float* gat_ar   = (const float*)d_in[15];
    const float* g2e_ah   = (const float*)d_in[16];
    const float* g2e_at   = (const float*)d_in[17];
    const float* g2e_ar   = (const float*)d_in[18];
    const int*   ei       = (const int*)d_in[19];   // [2,E]  rows: h, t
    const int*   rel      = (const int*)d_in[20];   // [E]
    const int*   eia      = (const int*)d_in[21];   // [2,EA] rows: j, i
    const int*   rel_all  = (const int*)d_in[22];   // [EA]
    const int*   lgm      = (const int*)d_in[23];   // [2,LG]
    const int*   lgt      = (const int*)d_in[24];   // [2,LG]
    float*       out      = (float*)d_out;

    // resolve scratch symbols
    float *px, *pt, *pagg, *pdeg, *pdinv, *penorm, *ppA, *ppB, *psm, *pew;
    float *pvi, *pvj, *pv2, *pal, *prsm, *prelA, *prelB, *prgate, *pxr, *pR2, *pR3;
    int *pmx, *prmx;
    cudaGetSymbolAddress((void**)&px, g_x);       cudaGetSymbolAddress((void**)&pt, g_t);
    cudaGetSymbolAddress((void**)&pagg, g_agg);   cudaGetSymbolAddress((void**)&pdeg, g_deg);
    cudaGetSymbolAddress((void**)&pdinv, g_dinv); cudaGetSymbolAddress((void**)&penorm, g_enorm);
    cudaGetSymbolAddress((void**)&ppA, g_pA);     cudaGetSymbolAddress((void**)&ppB, g_pB);
    cudaGetSymbolAddress((void**)&pmx, g_mx);     cudaGetSymbolAddress((void**)&psm, g_sm);
    cudaGetSymbolAddress((void**)&pew, g_ew);
    cudaGetSymbolAddress((void**)&pvi, g_vi);     cudaGetSymbolAddress((void**)&pvj, g_vj);
    cudaGetSymbolAddress((void**)&pv2, g_v2);     cudaGetSymbolAddress((void**)&pal, g_al);
    cudaGetSymbolAddress((void**)&prmx, g_rmx);   cudaGetSymbolAddress((void**)&prsm, g_rsm);
    cudaGetSymbolAddress((void**)&prelA, g_relA); cudaGetSymbolAddress((void**)&prelB, g_relB);
    cudaGetSymbolAddress((void**)&prgate, g_rgate); cudaGetSymbolAddress((void**)&pxr, g_xr);
    cudaGetSymbolAddress((void**)&pR2, g_projR2); cudaGetSymbolAddress((void**)&pR3, g_projR3);

    const int* eia_j = eia;            // sources
    const int* eia_i = eia + EA;       // destinations
    const int* ei_h  = ei;
    const int* ei_t  = ei + EE;

    dim3 gemmGbig(divup(DD, 64), divup(NN, 64));   // 5 x 1563
    dim3 gemmGrel(divup(RH, 64), divup(RRR, 64));  // 2 x 32

    // ---------- degrees & per-edge gcn norm (shared by both layers) ----------
    k_zero<<<divup(NN, TPB), TPB>>>(pdeg, NN);
    k_deg<<<divup(EA, TPB), TPB>>>(eia_i, pdeg, EA);
    k_dinv<<<divup(NN, TPB), TPB>>>(pdeg, pdinv, NN);
    k_enorm<<<divup(EA, TPB), TPB>>>(eia_j, eia_i, pdinv, penorm, EA);

    const long long ND = (long long)NN * DD;
    const long long ND4 = ND / 4;
    const int aggBlocks = divup((long long)EA * 32, TPB);

    // ---------- GCN layer 1 + highway ----------
    k_gemm_tc<<<gemmGbig, 256>>>(x_e, gcn1_w, nullptr, pt, NN, DD, DD);
    k_zero<<<divup(ND, TPB), TPB>>>(pagg, ND);
    k_wagg<<<aggBlocks, TPB>>>(eia_j, eia_i, penorm, pt, DD, pagg, DD, 0, DD, EA);
    k_gemm_tc<<<gemmGbig, 256>>>(x_e, hw1_w, hw1_b, pt, NN, DD, DD);
    k_highway4<<<divup(ND4, TPB), TPB>>>((const float4*)x_e, (const float4*)pagg,
                                         (const float4*)pt, (float4*)px, ND4, 1);

    // ---------- GCN layer 2 + highway ----------
    k_gemm_tc<<<gemmGbig, 256>>>(px, gcn2_w, nullptr, pt, NN, DD, DD);
    k_zero<<<divup(ND, TPB), TPB>>>(pagg, ND);
    k_wagg<<<aggBlocks, TPB>>>(eia_j, eia_i, penorm, pt, DD, pagg, DD, 0, DD, EA);
    k_gemm_tc<<<gemmGbig, 256>>>(px, hw2_w, hw2_b, pt, NN, DD, DD);
    k_highway4<<<divup(ND4, TPB), TPB>>>((const float4*)px, (const float4*)pagg,
                                         (const float4*)pt, (float4*)px, ND4, 1);

    // ---------- l_gat (merge and triangular) ----------
    const float* lg_x[2]   = { rel_out1, rel_tri1 };
    const int*   lg_ei[2]  = { lgm, lgt };
    const float* lg_val[2] = { merge_v, tri_v };
    float*       lg_out[2] = { prelA, prelB };
    for (int q = 0; q < 2; q++) {
        const int* lj = lg_ei[q];         // row 0 = j
        const int* li = lg_ei[q] + LG;    // row 1 = i
        const float* val = lg_val[q];
        // vi = softmax over i
        k_initseg<<<divup(RRR, TPB), TPB>>>(prmx, prsm, RRR);
        k_maxval<<<divup(LG, TPB), TPB>>>(val, li, prmx, LG);
        k_expval<<<divup(LG, TPB), TPB>>>(val, pvi, li, prmx, prsm, LG);
        k_div  <<<divup(LG, TPB), TPB>>>(pvi, li, prsm, LG);
        // vj = softmax over j
        k_initseg<<<divup(RRR, TPB), TPB>>>(prmx, prsm, RRR);
        k_maxval<<<divup(LG, TPB), TPB>>>(val, lj, prmx, LG);
        k_expval<<<divup(LG, TPB), TPB>>>(val, pvj, lj, prmx, prsm, LG);
        k_div  <<<divup(LG, TPB), TPB>>>(pvj, lj, prsm, LG);
        // alpha = softmax(vi+vj) over j
        k_add  <<<divup(LG, TPB), TPB>>>(pvi, pvj, pv2, LG);
        k_initseg<<<divup(RRR, TPB), TPB>>>(prmx, prsm, RRR);
        k_maxval<<<divup(LG, TPB), TPB>>>(pv2, lj, prmx, LG);
        k_expval<<<divup(LG, TPB), TPB>>>(pv2, pal, lj, prmx, prsm, LG);
        k_div  <<<divup(LG, TPB), TPB>>>(pal, lj, prsm, LG);
        // out[i] = relu(sum alpha * x[j])
        k_zero <<<divup((long long)RRR * RH, TPB), TPB>>>(lg_out[q], (long long)RRR * RH);
        k_wagg <<<divup((long long)LG * 32, TPB), TPB>>>(lj, li, pal, lg_x[q], RH,
                                                         lg_out[q], RH, 0, RH, LG);
        k_relu <<<divup((long long)RRR * RH, TPB), TPB>>>(lg_out[q], (long long)RRR * RH);
    }

    // ---------- x_r = highway(rel_merge, rel_tri) ----------
    k_gemm_tc<<<gemmGrel, 256>>>(prelA, hwr_w, hwr_b, prgate, RRR, RH, RH);
    k_highway4<<<divup((long long)RRR * RH / 4, TPB), TPB>>>(
        (const float4*)prelA, (const float4*)prelB, (const float4*)prgate,
        (float4*)pxr, (long long)RRR * RH / 4, 0);

    // ---------- entity GAT ----------
    k_dot2<<<divup((long long)NN * 32, TPB), TPB>>>(px, DD, gat_ai, gat_aj, ppA, ppB, NN, DD);
    k_projR2<<<divup((long long)2 * RRR * 32, TPB), TPB>>>(prelA, prelB, gat_ar, pR2);
    k_initseg<<<divup(NN, TPB), TPB>>>(pmx, psm, NN);
    k_score<<<divup(EA, TPB), TPB>>>(ppA, eia_i, ppB, eia_j, pR2, rel_all, eia_i, pew, pmx, EA);
    k_expval<<<divup(EA, TPB), TPB>>>(pew, pew, eia_i, pmx, psm, EA);
    k_div  <<<divup(EA, TPB), TPB>>>(pew, eia_i, psm, EA);
    // prep d_out (x into 0..299, zeros into 300..799), aggregate into 300..599, relu
    k_prep_out<<<divup((long long)NN * 800, TPB), TPB>>>(out, px);
    k_wagg <<<aggBlocks, TPB>>>(eia_j, eia_i, pew, px, DD, out, 800, 300, DD, EA);
    k_relu_str<<<divup((long long)NN * 300, TPB), TPB>>>(out, NN, 800, 300, 300);

    // ---------- relation -> entity GAT ----------
    k_dot2<<<divup((long long)NN * 32, TPB), TPB>>>(out, 800, g2e_ah, g2e_at, ppA, ppB, NN, 600);
    k_dot2<<<divup((long long)RRR * 32, TPB), TPB>>>(pxr, RH, g2e_ar, nullptr, pR3, nullptr, RRR, RH);

    // a1 over h -> cols 600..699
    k_initseg<<<divup(NN, TPB), TPB>>>(pmx, psm, NN);
    k_score<<<divup(EE, TPB), TPB>>>(ppA, ei_h, pR3, rel, nullptr, nullptr, ei_h, pew, pmx, EE);
    k_expval<<<divup(EE, TPB), TPB>>>(pew, pew, ei_h, pmx, psm, EE);
    k_div  <<<divup(EE, TPB), TPB>>>(pew, ei_h, psm, EE);
    k_wagg <<<divup((long long)EE * 32, TPB), TPB>>>(rel, ei_h, pew, pxr, RH, out, 800, 600, RH, EE);

    // a2 over t -> cols 700..799
    k_initseg<<<divup(NN, TPB), TPB>>>(pmx, psm, NN);
    k_score<<<divup(EE, TPB), TPB>>>(ppB, ei_t, pR3, rel, nullptr, nullptr, ei_t, pew, pmx, EE);
    k_expval<<<divup(EE, TPB), TPB>>>(pew, pew, ei_t, pmx, psm, EE);
    k_div  <<<divup(EE, TPB), TPB>>>(pew, ei_t, psm, EE);
    k_wagg <<<divup((long long)EE * 32, TPB), TPB>>>(rel, ei_t, pew, pxr, RH, out, 800, 700, RH, EE);

    (void)in_sizes; (void)n_in; (void)out_size;
}

// round 8
// speedup vs baseline: 1.6564x; 1.6564x over previous
#include <cuda_runtime.h>
#include <cuda_bf16.h>
#include <mma.h>
#include <math.h>

using namespace nvcuda;

// Problem constants (fixed by the dataset)
#define NN   100000   // entities
#define DD   300      // e_hidden
#define EE   400000   // triples (KG1)
#define EA   800000   // symmetric all-edge count (2*EH)
#define RRR  2000     // relations
#define RH   100      // r_hidden
#define LG   60000    // line-graph edges
#define KP   304      // padded K for big GEMMs (300 -> 304, mult of 16)
#define KPR  112      // padded K for relation GEMM (100 -> 112)

static const int TPB = 256;

// ---------------- device scratch (static globals; no allocation) -------------
__device__ float g_x   [(size_t)NN*DD];   // current entity features
__device__ float g_t   [(size_t)NN*DD];   // GEMM output (xw / gate pre-sigmoid)
__device__ float g_agg [(size_t)NN*DD];   // aggregation accumulator
__device__ float g_deg [NN];
__device__ float g_dinv[NN];
__device__ float g_enorm[EA];             // per-edge gcn norm (reused both layers)
__device__ float g_pA  [NN];              // per-node projections
__device__ float g_pB  [NN];
__device__ int   g_mx  [NN];              // segment max (encoded)
__device__ float g_sm  [NN];              // segment sum
__device__ float g_ew  [EA];              // per-edge scratch (scores -> p -> alpha)
__device__ float g_vi  [LG];
__device__ float g_vj  [LG];
__device__ float g_v2  [LG];
__device__ float g_al  [LG];
__device__ int   g_rmx [RRR];
__device__ float g_rsm [RRR];
__device__ float g_relA[RRR*RH];          // rel_merge
__device__ float g_relB[RRR*RH];          // rel_tri
__device__ float g_rgate[RRR*RH];
__device__ float g_xr  [RRR*RH];          // highway(rel_merge, rel_tri)
__device__ float g_projR2[2*RRR];         // (rel_emb @ a_r) for GAT
__device__ float g_projR3[RRR];           // (x_r @ g2e_ar)
// split-bf16 staging for tensor-core GEMMs
__device__ __nv_bfloat16 g_Ah[(size_t)NN*KP];
__device__ __nv_bfloat16 g_Al[(size_t)NN*KP];
__device__ __nv_bfloat16 g_Bh[(size_t)DD*KP];
__device__ __nv_bfloat16 g_Bl[(size_t)DD*KP];

// ---------------- helpers ----------------------------------------------------
__device__ __forceinline__ int encf(float f) {
    int i = __float_as_int(f);
    return i >= 0 ? i : (i ^ 0x7fffffff);
}
__device__ __forceinline__ float decf(int i) {
    return __int_as_float(i >= 0 ? i : (i ^ 0x7fffffff));
}
// 16B vector atomic add (sm_90+); all destinations proven 16B-aligned.
__device__ __forceinline__ void red4(float* p, float a, float b, float c, float d) {
    asm volatile("red.global.add.v4.f32 [%0], {%1, %2, %3, %4};"
                 :: "l"(p), "f"(a), "f"(b), "f"(c), "f"(d) : "memory");
}

// ---------------- elementwise / init -----------------------------------------
__global__ void k_zero(float* p, long long n) {
    long long i = blockIdx.x * (long long)blockDim.x + threadIdx.x;
    if (i < n) p[i] = 0.f;
}
__global__ void k_initseg(int* mx, float* sm, int n) {
    int i = blockIdx.x * blockDim.x + threadIdx.x;
    if (i < n) { mx[i] = 0x80000000; sm[i] = 0.f; }
}

// ---------------- split fp32 -> (hi, lo) bf16, zero-padded to Kp --------------
__global__ void k_split(const float* __restrict__ in, __nv_bfloat16* __restrict__ hi,
                        __nv_bfloat16* __restrict__ lo, int n, int K, int Kp) {
    long long i = blockIdx.x * (long long)blockDim.x + threadIdx.x;
    if (i >= (long long)n * Kp) return;
    int r = (int)(i / Kp), c = (int)(i % Kp);
    float v = (c < K) ? in[(size_t)r * K + c] : 0.f;
    __nv_bfloat16 h = __float2bfloat16(v);
    hi[i] = h;
    lo[i] = __float2bfloat16(v - __bfloat162float(h));
}

// ---------------- degree / norm ----------------------------------------------
__global__ void k_deg(const int* __restrict__ dst, float* deg, int ne) {
    int e = blockIdx.x * blockDim.x + threadIdx.x;
    if (e < ne) atomicAdd(&deg[dst[e]], 1.f);
}
__global__ void k_dinv(const float* __restrict__ deg, float* dinv, int n) {
    int i = blockIdx.x * blockDim.x + threadIdx.x;
    if (i < n) { float d = deg[i]; dinv[i] = d > 0.f ? rsqrtf(d) : 0.f; }
}
__global__ void k_enorm(const int* __restrict__ js, const int* __restrict__ is,
                        const float* __restrict__ dinv, float* en, int ne) {
    int e = blockIdx.x * blockDim.x + threadIdx.x;
    if (e < ne) en[e] = dinv[js[e]] * dinv[is[e]];
}

// ---- GEMM (tensor core, split-bf16 3-MMA, pre-converted operands) -----------
// Out[n,m] = A[n,K] @ B[m,K]^T (+bias), A = Ah+Al, B = Bh+Bl (bf16 pairs).
// acc += Ah*Bh + Ah*Bl + Al*Bh, fp32 accumulate. Block tile 128x64, 8 warps.
// Shared: tile buffers (18.0 KB) and epilogue stage (32 KB) ALIAS each other
// (tiles dead after mainloop; __syncthreads separates) -> 32 KB static smem.
__global__ __launch_bounds__(256) void k_gemm_bf3(
        const __nv_bfloat16* __restrict__ Ah, const __nv_bfloat16* __restrict__ Al,
        const __nv_bfloat16* __restrict__ Bh, const __nv_bfloat16* __restrict__ Bl,
        const float* __restrict__ bias, float* __restrict__ Out,
        int n, int m, int Kp) {
    __shared__ __align__(16) unsigned char sbuf[128 * 64 * 4];
    typedef __nv_bfloat16 row24[24];
    row24* Ahs = reinterpret_cast<row24*>(sbuf);             // 128x24 = 6144 B
    row24* Als = reinterpret_cast<row24*>(sbuf + 6144);      // 128x24 = 6144 B
    row24* Bhs = reinterpret_cast<row24*>(sbuf + 12288);     //  64x24 = 3072 B
    row24* Bls = reinterpret_cast<row24*>(sbuf + 15360);     //  64x24 = 3072 B
    float* stage = reinterpret_cast<float*>(sbuf);           // 128x64 fp32 (after loop)

    const int tid = threadIdx.x;
    const int wid = tid >> 5;
    const int wr  = wid & 3;       // warp row 0..3  (32 output rows each)
    const int wc  = wid >> 2;      // warp col 0..1  (32 output cols each)
    const int rb  = blockIdx.y * 128, cb = blockIdx.x * 64;

    // loader mapping (steady state, no conversions, vector ld/st)
    const int ar  = tid >> 1;              // A tile row 0..127
    const int ak  = (tid & 1) * 8;         // k offset 0 / 8
    const int brr = tid >> 2;              // B tile row 0..63
    const int bk  = (tid & 3) * 4;         // k offset 0,4,8,12
    const size_t aoff = (size_t)min(rb + ar, n - 1) * Kp + ak;
    const size_t boff = (size_t)min(cb + brr, m - 1) * Kp + bk;

    wmma::fragment<wmma::accumulator, 16, 16, 16, float> acc[2][2];
#pragma unroll
    for (int i = 0; i < 2; i++)
#pragma unroll
        for (int j = 0; j < 2; j++) wmma::fill_fragment(acc[i][j], 0.f);

    uint4 rah = *(const uint4*)(Ah + aoff);
    uint4 ral = *(const uint4*)(Al + aoff);
    uint2 rbh = *(const uint2*)(Bh + boff);
    uint2 rbl = *(const uint2*)(Bl + boff);

    for (int k0 = 0; k0 < Kp; k0 += 16) {
        *(uint4*)&Ahs[ar][ak] = rah;
        *(uint4*)&Als[ar][ak] = ral;
        *(uint2*)&Bhs[brr][bk] = rbh;
        *(uint2*)&Bls[brr][bk] = rbl;
        __syncthreads();
        if (k0 + 16 < Kp) {
            rah = *(const uint4*)(Ah + aoff + k0 + 16);
            ral = *(const uint4*)(Al + aoff + k0 + 16);
            rbh = *(const uint2*)(Bh + boff + k0 + 16);
            rbl = *(const uint2*)(Bl + boff + k0 + 16);
        }
        wmma::fragment<wmma::matrix_a, 16, 16, 16, __nv_bfloat16, wmma::row_major> fah[2], fal[2];
        wmma::fragment<wmma::matrix_b, 16, 16, 16, __nv_bfloat16, wmma::col_major> fbh[2], fbl[2];
#pragma unroll
        for (int i = 0; i < 2; i++) {
            wmma::load_matrix_sync(fah[i], &Ahs[wr * 32 + 16 * i][0], 24);
            wmma::load_matrix_sync(fal[i], &Als[wr * 32 + 16 * i][0], 24);
        }
#pragma unroll
        for (int j = 0; j < 2; j++) {
            wmma::load_matrix_sync(fbh[j], &Bhs[wc * 32 + 16 * j][0], 24);
            wmma::load_matrix_sync(fbl[j], &Bls[wc * 32 + 16 * j][0], 24);
        }
#pragma unroll
        for (int i = 0; i < 2; i++)
#pragma unroll
            for (int j = 0; j < 2; j++) {
                wmma::mma_sync(acc[i][j], fah[i], fbh[j], acc[i][j]);
                wmma::mma_sync(acc[i][j], fah[i], fbl[j], acc[i][j]);
                wmma::mma_sync(acc[i][j], fal[i], fbh[j], acc[i][j]);
            }
        __syncthreads();
    }

    // epilogue: stage aliases tile buffers (safe after the final __syncthreads)
#pragma unroll
    for (int i = 0; i < 2; i++)
#pragma unroll
        for (int j = 0; j < 2; j++)
            wmma::store_matrix_sync(&stage[(wr * 32 + 16 * i) * 64 + wc * 32 + 16 * j],
                                    acc[i][j], 64, wmma::mem_row_major);
    __syncthreads();

    // 128x64 tile -> global with bounds; float4 lanes (m mult of 4)
    for (int s = tid; s < 128 * 16; s += 256) {
        int rr = s >> 4, c4 = (s & 15) * 4;
        int gr = rb + rr, gc = cb + c4;
        if (gr < n && gc < m) {
            float4 v = *(const float4*)&stage[rr * 64 + c4];
            if (bias) { v.x += bias[gc]; v.y += bias[gc+1]; v.z += bias[gc+2]; v.w += bias[gc+3]; }
            *(float4*)&Out[(size_t)gr * m + gc] = v;
        }
    }
}

// ---- weighted scatter-add: out[dst[e], ofs:ofs+D] += w[e]*X[src[e],:D] ------
__global__ void k_wagg(const int* __restrict__ srcIdx, const int* __restrict__ dstIdx,
                       const float* __restrict__ w, const float* __restrict__ X,
                       int ss, float* out, int os, int ofs, int D, int ne) {
    int e    = (int)((blockIdx.x * (long long)blockDim.x + threadIdx.x) >> 5);
    int lane = threadIdx.x & 31;
    if (e >= ne) return;
    float wt = w[e];
    const float4* src = reinterpret_cast<const float4*>(X + (size_t)srcIdx[e] * ss);
    float* dst = out + (size_t)dstIdx[e] * os + ofs;
    int D4 = D >> 2;
    for (int c = lane; c < D4; c += 32) {
        float4 v = src[c];
        red4(dst + c * 4, wt * v.x, wt * v.y, wt * v.z, wt * v.w);
    }
}

// ---------------- highway combine (float4) -----------------------------------
__global__ void k_highway4(const float4* __restrict__ xin, const float4* __restrict__ x2,
                           const float4* __restrict__ gate, float4* out, long long n4, int relu2) {
    long long i = blockIdx.x * (long long)blockDim.x + threadIdx.x;
    if (i >= n4) return;
    float4 gv = gate[i], bv = x2[i], av = xin[i], o;
    float g;
    g = 1.f / (1.f + expf(-gv.x)); o.x = g * (relu2 ? fmaxf(bv.x, 0.f) : bv.x) + (1.f - g) * av.x;
    g = 1.f / (1.f + expf(-gv.y)); o.y = g * (relu2 ? fmaxf(bv.y, 0.f) : bv.y) + (1.f - g) * av.y;
    g = 1.f / (1.f + expf(-gv.z)); o.z = g * (relu2 ? fmaxf(bv.z, 0.f) : bv.z) + (1.f - g) * av.z;
    g = 1.f / (1.f + expf(-gv.w)); o.w = g * (relu2 ? fmaxf(bv.w, 0.f) : bv.w) + (1.f - g) * av.w;
    out[i] = o;
}

// ---------------- segment softmax primitives ---------------------------------
__global__ void k_maxval(const float* __restrict__ val, const int* __restrict__ seg,
                         int* mx, int ne) {
    int e = blockIdx.x * blockDim.x + threadIdx.x;
    if (e < ne) atomicMax(&mx[seg[e]], encf(val[e]));
}
__global__ void k_expval(const float* __restrict__ vin, float* pout,
                         const int* __restrict__ seg, const int* __restrict__ mx,
                         float* sm, int ne) {
    int e = blockIdx.x * blockDim.x + threadIdx.x;
    if (e >= ne) return;
    float p = expf(vin[e] - decf(mx[seg[e]]));
    pout[e] = p;
    atomicAdd(&sm[seg[e]], p);
}
__global__ void k_div(float* p, const int* __restrict__ seg,
                      const float* __restrict__ sm, int ne) {
    int e = blockIdx.x * blockDim.x + threadIdx.x;
    if (e < ne) p[e] = p[e] / (sm[seg[e]] + 1e-16f);
}
__global__ void k_add(const float* a, const float* b, float* o, int ne) {
    int e = blockIdx.x * blockDim.x + threadIdx.x;
    if (e < ne) o[e] = a[e] + b[e];
}

// GAT-style edge score: v = pa[ia] + pb[ib] (+ pc[ic]); leaky_relu; store + seg-max
__global__ void k_score(const float* __restrict__ pa, const int* __restrict__ ia,
                        const float* __restrict__ pb, const int* __restrict__ ib,
                        const float* __restrict__ pc, const int* __restrict__ ic,
                        const int* __restrict__ seg, float* out, int* mx, int ne) {
    int e = blockIdx.x * blockDim.x + threadIdx.x;
    if (e >= ne) return;
    float v = pa[ia[e]] + pb[ib[e]];
    if (pc) v += pc[ic[e]];
    v = v >= 0.f ? v : 0.01f * v;
    out[e] = v;
    atomicMax(&mx[seg[e]], encf(v));
}

// ---------------- relu / output prep -----------------------------------------
__global__ void k_relu(float* p, long long n) {
    long long i = blockIdx.x * (long long)blockDim.x + threadIdx.x;
    if (i < n) p[i] = fmaxf(p[i], 0.f);
}
// one pass over d_out: cols 0..299 <- x, cols 300..799 <- 0
__global__ void k_prep_out(float* out, const float* __restrict__ x) {
    long long i = blockIdx.x * (long long)blockDim.x + threadIdx.x;
    long long n = (long long)NN * 800;
    if (i >= n) return;
    int r = (int)(i / 800), c = (int)(i % 800);
    out[i] = (c < DD) ? x[(size_t)r * DD + c] : 0.f;
}
__global__ void k_relu_str(float* out, int rows, int rstride, int ofs, int D) {
    long long i = blockIdx.x * (long long)blockDim.x + threadIdx.x;
    long long n = (long long)rows * D;
    if (i >= n) return;
    int r = (int)(i / D), c = (int)(i % D);
    size_t p = (size_t)r * rstride + ofs + c;
    out[p] = fmaxf(out[p], 0.f);
}

// ---------------- per-row dot products (warp per row) ------------------------
__global__ void k_dot2(const float* __restrict__ X, int stride,
                       const float* __restrict__ a, const float* __restrict__ b,
                       float* outA, float* outB, int n, int D) {
    int w    = (int)((blockIdx.x * (long long)blockDim.x + threadIdx.x) >> 5);
    int lane = threadIdx.x & 31;
    if (w >= n) return;
    const float* row = X + (size_t)w * stride;
    float sa = 0.f, sb = 0.f;
    for (int c = lane; c < D; c += 32) {
        float x = row[c];
        sa += x * a[c];
        if (b) sb += x * b[c];
    }
#pragma unroll
    for (int o = 16; o; o >>= 1) {
        sa += __shfl_down_sync(0xffffffffu, sa, o);
        if (b) sb += __shfl_down_sync(0xffffffffu, sb, o);
    }
    if (lane == 0) { outA[w] = sa; if (b) outB[w] = sb; }
}

// proj over rel_emb = concat([rel_cat, rel_cat], axis=0), rel_cat = [merge|tri]
__global__ void k_projR2(const float* __restrict__ relA, const float* __restrict__ relB,
                         const float* __restrict__ ar, float* out) {
    int w    = (int)((blockIdx.x * (long long)blockDim.x + threadIdx.x) >> 5);
    int lane = threadIdx.x & 31;
    if (w >= 2 * RRR) return;
    int r = w < RRR ? w : w - RRR;
    float s = 0.f;
    for (int c = lane; c < RH; c += 32)
        s += relA[(size_t)r * RH + c] * ar[c] + relB[(size_t)r * RH + c] * ar[RH + c];
#pragma unroll
    for (int o = 16; o; o >>= 1) s += __shfl_down_sync(0xffffffffu, s, o);
    if (lane == 0) out[w] = s;
}

// ---------------- host orchestration -----------------------------------------
static inline int divup(long long a, int b) { return (int)((a + b - 1) / b); }

extern "C" void kernel_launch(void* const* d_in, const int* in_sizes, int n_in,
                              void* d_out, int out_size) {
    const float* x_e      = (const float*)d_in[0];
    const float* merge_v  = (const float*)d_in[1];
    const float* tri_v    = (const float*)d_in[2];
    const float* gcn1_w   = (const float*)d_in[3];
    const float* hw1_w    = (const float*)d_in[4];
    const float* hw1_b    = (const float*)d_in[5];
    const float* gcn2_w   = (const float*)d_in[6];
    const float* hw2_w    = (const float*)d_in[7];
    const float* hw2_b    = (const float*)d_in[8];
    const float* rel_out1 = (const float*)d_in[9];
    const float* rel_tri1 = (const float*)d_in[10];
    const float* hwr_w    = (const float*)d_in[11];
    const float* hwr_b    = (const float*)d_in[12];
    const float* gat_ai   = (const float*)d_in[13];
    const float* gat_aj   = (const float*)d_in[14];
    const float* gat_ar   = (const float*)d_in[15];
    const float* g2e_ah   = (const float*)d_in[16];
    const float* g2e_at   = (const float*)d_in[17];
    const float* g2e_ar   = (const float*)d_in[18];
    const int*   ei       = (const int*)d_in[19];   // [2,E]  rows: h, t
    const int*   rel      = (const int*)d_in[20];   // [E]
    const int*   eia      = (const int*)d_in[21];   // [2,EA] rows: j, i
    const int*   rel_all  = (const int*)d_in[22];   // [EA]
    const int*   lgm      = (const int*)d_in[23];   // [2,LG]
    const int*   lgt      = (const int*)d_in[24];   // [2,LG]
    float*       out      = (float*)d_out;

    // resolve scratch symbols
    float *px, *pt, *pagg, *pdeg, *pdinv, *penorm, *ppA, *ppB, *psm, *pew;
    float *pvi, *pvj, *pv2, *pal, *prsm, *prelA, *prelB, *prgate, *pxr, *pR2, *pR3;
    int *pmx, *prmx;
    __nv_bfloat16 *pAh, *pAl, *pBh, *pBl;
    cudaGetSymbolAddress((void**)&px, g_x);       cudaGetSymbolAddress((void**)&pt, g_t);
    cudaGetSymbolAddress((void**)&pagg, g_agg);   cudaGetSymbolAddress((void**)&pdeg, g_deg);
    cudaGetSymbolAddress((void**)&pdinv, g_dinv); cudaGetSymbolAddress((void**)&penorm, g_enorm);
    cudaGetSymbolAddress((void**)&ppA, g_pA);     cudaGetSymbolAddress((void**)&ppB, g_pB);
    cudaGetSymbolAddress((void**)&pmx, g_mx);     cudaGetSymbolAddress((void**)&psm, g_sm);
    cudaGetSymbolAddress((void**)&pew, g_ew);
    cudaGetSymbolAddress((void**)&pvi, g_vi);     cudaGetSymbolAddress((void**)&pvj, g_vj);
    cudaGetSymbolAddress((void**)&pv2, g_v2);     cudaGetSymbolAddress((void**)&pal, g_al);
    cudaGetSymbolAddress((void**)&prmx, g_rmx);   cudaGetSymbolAddress((void**)&prsm, g_rsm);
    cudaGetSymbolAddress((void**)&prelA, g_relA); cudaGetSymbolAddress((void**)&prelB, g_relB);
    cudaGetSymbolAddress((void**)&prgate, g_rgate); cudaGetSymbolAddress((void**)&pxr, g_xr);
    cudaGetSymbolAddress((void**)&pR2, g_projR2); cudaGetSymbolAddress((void**)&pR3, g_projR3);
    cudaGetSymbolAddress((void**)&pAh, g_Ah);     cudaGetSymbolAddress((void**)&pAl, g_Al);
    cudaGetSymbolAddress((void**)&pBh, g_Bh);     cudaGetSymbolAddress((void**)&pBl, g_Bl);

    const int* eia_j = eia;            // sources
    const int* eia_i = eia + EA;       // destinations
    const int* ei_h  = ei;
    const int* ei_t  = ei + EE;

    dim3 gemmGbig(divup(DD, 64), divup(NN, 128));    // 5 x 782
    dim3 gemmGrel(divup(RH, 64), divup(RRR, 128));   // 2 x 16
    const long long splitBig = (long long)NN * KP;
    const long long splitW   = (long long)DD * KP;
    const long long splitAr  = (long long)RRR * KPR;
    const long long splitWr  = (long long)RH * KPR;

    // ---------- degrees & per-edge gcn norm (shared by both layers) ----------
    k_zero<<<divup(NN, TPB), TPB>>>(pdeg, NN);
    k_deg<<<divup(EA, TPB), TPB>>>(eia_i, pdeg, EA);
    k_dinv<<<divup(NN, TPB), TPB>>>(pdeg, pdinv, NN);
    k_enorm<<<divup(EA, TPB), TPB>>>(eia_j, eia_i, pdinv, penorm, EA);

    const long long ND = (long long)NN * DD;
    const long long ND4 = ND / 4;
    const int aggBlocks = divup((long long)EA * 32, TPB);

    // ---------- GCN layer 1 + highway ----------
    k_split<<<divup(splitBig, TPB), TPB>>>(x_e, pAh, pAl, NN, DD, KP);
    k_split<<<divup(splitW, TPB), TPB>>>(gcn1_w, pBh, pBl, DD, DD, KP);
    k_gemm_bf3<<<gemmGbig, 256>>>(pAh, pAl, pBh, pBl, nullptr, pt, NN, DD, KP);
    k_zero<<<divup(ND, TPB), TPB>>>(pagg, ND);
    k_wagg<<<aggBlocks, TPB>>>(eia_j, eia_i, penorm, pt, DD, pagg, DD, 0, DD, EA);
    k_split<<<divup(splitW, TPB), TPB>>>(hw1_w, pBh, pBl, DD, DD, KP);
    k_gemm_bf3<<<gemmGbig, 256>>>(pAh, pAl, pBh, pBl, hw1_b, pt, NN, DD, KP);
    k_highway4<<<divup(ND4, TPB), TPB>>>((const float4*)x_e, (const float4*)pagg,
                                         (const float4*)pt, (float4*)px, ND4, 1);

    // ---------- GCN layer 2 + highway ----------
    k_split<<<divup(splitBig, TPB), TPB>>>(px, pAh, pAl, NN, DD, KP);
    k_split<<<divup(splitW, TPB), TPB>>>(gcn2_w, pBh, pBl, DD, DD, KP);
    k_gemm_bf3<<<gemmGbig, 256>>>(pAh, pAl, pBh, pBl, nullptr, pt, NN, DD, KP);
    k_zero<<<divup(ND, TPB), TPB>>>(pagg, ND);
    k_wagg<<<aggBlocks, TPB>>>(eia_j, eia_i, penorm, pt, DD, pagg, DD, 0, DD, EA);
    k_split<<<divup(splitW, TPB), TPB>>>(hw2_w, pBh, pBl, DD, DD, KP);
    k_gemm_bf3<<<gemmGbig, 256>>>(pAh, pAl, pBh, pBl, hw2_b, pt, NN, DD, KP);
    k_highway4<<<divup(ND4, TPB), TPB>>>((const float4*)px, (const float4*)pagg,
                                         (const float4*)pt, (float4*)px, ND4, 1);

    // ---------- l_gat (merge and triangular) ----------
    const float* lg_x[2]   = { rel_out1, rel_tri1 };
    const int*   lg_ei[2]  = { lgm, lgt };
    const float* lg_val[2] = { merge_v, tri_v };
    float*       lg_out[2] = { prelA, prelB };
    for (int q = 0; q < 2; q++) {
        const int* lj = lg_ei[q];         // row 0 = j
        const int* li = lg_ei[q] + LG;    // row 1 = i
        const float* val = lg_val[q];
        // vi = softmax over i
        k_initseg<<<divup(RRR, TPB), TPB>>>(prmx, prsm, RRR);
        k_maxval<<<divup(LG, TPB), TPB>>>(val, li, prmx, LG);
        k_expval<<<divup(LG, TPB), TPB>>>(val, pvi, li, prmx, prsm, LG);
        k_div  <<<divup(LG, TPB), TPB>>>(pvi, li, prsm, LG);
        // vj = softmax over j
        k_initseg<<<divup(RRR, TPB), TPB>>>(prmx, prsm, RRR);
        k_maxval<<<divup(LG, TPB), TPB>>>(val, lj, prmx, LG);
        k_expval<<<divup(LG, TPB), TPB>>>(val, pvj, lj, prmx, prsm, LG);
        k_div  <<<divup(LG, TPB), TPB>>>(pvj, lj, prsm, LG);
        // alpha = softmax(vi+vj) over j
        k_add  <<<divup(LG, TPB), TPB>>>(pvi, pvj, pv2, LG);
        k_initseg<<<divup(RRR, TPB), TPB>>>(prmx, prsm, RRR);
        k_maxval<<<divup(LG, TPB), TPB>>>(pv2, lj, prmx, LG);
        k_expval<<<divup(LG, TPB), TPB>>>(pv2, pal, lj, prmx, prsm, LG);
        k_div  <<<divup(LG, TPB), TPB>>>(pal, lj, prsm, LG);
        // out[i] = relu(sum alpha * x[j])
        k_zero <<<divup((long long)RRR * RH, TPB), TPB>>>(lg_out[q], (long long)RRR * RH);
        k_wagg <<<divup((long long)LG * 32, TPB), TPB>>>(lj, li, pal, lg_x[q], RH,
                                                         lg_out[q], RH, 0, RH, LG);
        k_relu <<<divup((long long)RRR * RH, TPB), TPB>>>(lg_out[q], (long long)RRR * RH);
    }

    // ---------- x_r = highway(rel_merge, rel_tri) ----------
    k_split<<<divup(splitAr, TPB), TPB>>>(prelA, pAh, pAl, RRR, RH, KPR);
    k_split<<<divup(splitWr, TPB), TPB>>>(hwr_w, pBh, pBl, RH, RH, KPR);
    k_gemm_bf3<<<gemmGrel, 256>>>(pAh, pAl, pBh, pBl, hwr_b, prgate, RRR, RH, KPR);
    k_highway4<<<divup((long long)RRR * RH / 4, TPB), TPB>>>(
        (const float4*)prelA, (const float4*)prelB, (const float4*)prgate,
        (float4*)pxr, (long long)RRR * RH / 4, 0);

    // ---------- entity GAT ----------
    k_dot2<<<divup((long long)NN * 32, TPB), TPB>>>(px, DD, gat_ai, gat_aj, ppA, ppB, NN, DD);
    k_projR2<<<divup((long long)2 * RRR * 32, TPB), TPB>>>(prelA, prelB, gat_ar, pR2);
    k_initseg<<<divup(NN, TPB), TPB>>>(pmx, psm, NN);
    k_score<<<divup(EA, TPB), TPB>>>(ppA, eia_i, ppB, eia_j, pR2, rel_all, eia_i, pew, pmx, EA);
    k_expval<<<divup(EA, TPB), TPB>>>(pew, pew, eia_i, pmx, psm, EA);
    k_div  <<<divup(EA, TPB), TPB>>>(pew, eia_i, psm, EA);
    // prep d_out (x into 0..299, zeros into 300..799), aggregate into 300..599, relu
    k_prep_out<<<divup((long long)NN * 800, TPB), TPB>>>(out, px);
    k_wagg <<<aggBlocks, TPB>>>(eia_j, eia_i, pew, px, DD, out, 800, 300, DD, EA);
    k_relu_str<<<divup((long long)NN * 300, TPB), TPB>>>(out, NN, 800, 300, 300);

    // ---------- relation -> entity GAT ----------
    k_dot2<<<divup((long long)NN * 32, TPB), TPB>>>(out, 800, g2e_ah, g2e_at, ppA, ppB, NN, 600);
    k_dot2<<<divup((long long)RRR * 32, TPB), TPB>>>(pxr, RH, g2e_ar, nullptr, pR3, nullptr, RRR, RH);

    // a1 over h -> cols 600..699
    k_initseg<<<divup(NN, TPB), TPB>>>(pmx, psm, NN);
    k_score<<<divup(EE, TPB), TPB>>>(ppA, ei_h, pR3, rel, nullptr, nullptr, ei_h, pew, pmx, EE);
    k_expval<<<divup(EE, TPB), TPB>>>(pew, pew, ei_h, pmx, psm, EE);
    k_div  <<<divup(EE, TPB), TPB>>>(pew, ei_h, psm, EE);
    k_wagg <<<divup((long long)EE * 32, TPB), TPB>>>(rel, ei_h, pew, pxr, RH, out, 800, 600, RH, EE);

    // a2 over t -> cols 700..799
    k_initseg<<<divup(NN, TPB), TPB>>>(pmx, psm, NN);
    k_score<<<divup(EE, TPB), TPB>>>(ppB, ei_t, pR3, rel, nullptr, nullptr, ei_t, pew, pmx, EE);
    k_expval<<<divup(EE, TPB), TPB>>>(pew, pew, ei_t, pmx, psm, EE);
    k_div  <<<divup(EE, TPB), TPB>>>(pew, ei_t, psm, EE);
    k_wagg <<<divup((long long)EE * 32, TPB), TPB>>>(rel, ei_t, pew, pxr, RH, out, 800, 700, RH, EE);

    (void)in_sizes; (void)n_in; (void)out_size;
}

// round 10
// speedup vs baseline: 1.7511x; 1.0572x over previous
#include <cuda_runtime.h>
#include <cuda_bf16.h>
#include <mma.h>
#include <math.h>

using namespace nvcuda;

// Problem constants (fixed by the dataset)
#define NN   100000   // entities
#define DD   300      // e_hidden
#define EE   400000   // triples (KG1)
#define EA   800000   // symmetric all-edge count (2*EH)
#define RRR  2000     // relations
#define RH   100      // r_hidden
#define LG   60000    // line-graph edges
#define KP   304      // padded K for big GEMMs (300 -> 304, mult of 16)
#define KPR  112      // padded K for relation GEMM (100 -> 112)

static const int TPB = 256;

// ---------------- device scratch (static globals; no allocation) -------------
__device__ float g_x   [(size_t)NN*DD];
__device__ float g_t   [(size_t)NN*DD];
__device__ float g_agg [(size_t)NN*DD];
__device__ float g_deg [NN];
__device__ float g_dinv[NN];
__device__ float g_enorm[EA];
__device__ float g_pA  [NN];
__device__ float g_pB  [NN];
__device__ int   g_mx  [NN];
__device__ float g_sm  [NN];
__device__ float g_ew  [EA];
__device__ float g_vi  [LG];
__device__ float g_vj  [LG];
__device__ float g_v2  [LG];
__device__ float g_al  [LG];
__device__ int   g_rmx [RRR];
__device__ float g_rsm [RRR];
__device__ float g_relA[RRR*RH];
__device__ float g_relB[RRR*RH];
__device__ float g_rgate[RRR*RH];
__device__ float g_xr  [RRR*RH];
__device__ float g_projR2[2*RRR];
__device__ float g_projR3[RRR];
__device__ __nv_bfloat16 g_Ah[(size_t)NN*KP];
__device__ __nv_bfloat16 g_Al[(size_t)NN*KP];
__device__ __nv_bfloat16 g_Bh[(size_t)DD*KP];
__device__ __nv_bfloat16 g_Bl[(size_t)DD*KP];

// ---------------- helpers ----------------------------------------------------
__device__ __forceinline__ int encf(float f) {
    int i = __float_as_int(f);
    return i >= 0 ? i : (i ^ 0x7fffffff);
}
__device__ __forceinline__ float decf(int i) {
    return __int_as_float(i >= 0 ? i : (i ^ 0x7fffffff));
}
__device__ __forceinline__ void red4(float* p, float a, float b, float c, float d) {
    asm volatile("red.global.add.v4.f32 [%0], {%1, %2, %3, %4};"
                 :: "l"(p), "f"(a), "f"(b), "f"(c), "f"(d) : "memory");
}
__device__ __forceinline__ void split4(float4 v, __nv_bfloat16* h, __nv_bfloat16* l) {
    h[0] = __float2bfloat16(v.x); l[0] = __float2bfloat16(v.x - __bfloat162float(h[0]));
    h[1] = __float2bfloat16(v.y); l[1] = __float2bfloat16(v.y - __bfloat162float(h[1]));
    h[2] = __float2bfloat16(v.z); l[2] = __float2bfloat16(v.z - __bfloat162float(h[2]));
    h[3] = __float2bfloat16(v.w); l[3] = __float2bfloat16(v.w - __bfloat162float(h[3]));
}

// ---------------- elementwise / init -----------------------------------------
__global__ void k_zero(float* p, long long n) {
    long long i = blockIdx.x * (long long)blockDim.x + threadIdx.x;
    if (i < n) p[i] = 0.f;
}
__global__ void k_initseg(int* mx, float* sm, int n) {
    int i = blockIdx.x * blockDim.x + threadIdx.x;
    if (i < n) { mx[i] = 0x80000000; sm[i] = 0.f; }
}

// ------- split fp32 -> (hi, lo) bf16, zero-padded to Kp (float4 path) --------
__global__ void k_split(const float* __restrict__ in, __nv_bfloat16* __restrict__ hi,
                        __nv_bfloat16* __restrict__ lo, int n, int K, int Kp) {
    long long i = blockIdx.x * (long long)blockDim.x + threadIdx.x;
    int kp4 = Kp >> 2;
    if (i >= (long long)n * kp4) return;
    int r = (int)(i / kp4), c = (int)(i % kp4) * 4;
    float4 v = make_float4(0.f, 0.f, 0.f, 0.f);
    if (c + 3 < K) v = *(const float4*)(in + (size_t)r * K + c);
    __nv_bfloat16 h[4], l[4];
    split4(v, h, l);
    *(uint2*)(hi + (size_t)r * Kp + c) = *(uint2*)h;
    *(uint2*)(lo + (size_t)r * Kp + c) = *(uint2*)l;
}

// ---------------- degree / norm ----------------------------------------------
__global__ void k_deg(const int* __restrict__ dst, float* deg, int ne) {
    int e = blockIdx.x * blockDim.x + threadIdx.x;
    if (e < ne) atomicAdd(&deg[dst[e]], 1.f);
}
__global__ void k_dinv(const float* __restrict__ deg, float* dinv, int n) {
    int i = blockIdx.x * blockDim.x + threadIdx.x;
    if (i < n) { float d = deg[i]; dinv[i] = d > 0.f ? rsqrtf(d) : 0.f; }
}
__global__ void k_enorm(const int* __restrict__ js, const int* __restrict__ is,
                        const float* __restrict__ dinv, float* en, int ne) {
    int e = blockIdx.x * blockDim.x + threadIdx.x;
    if (e < ne) en[e] = dinv[js[e]] * dinv[is[e]];
}

// ---- GEMM (tensor core, split-bf16 3-MMA, double-buffered smem) -------------
// Out[n,m] = A[n,K] @ B[m,K]^T (+bias). acc += Ah*Bh + Ah*Bl + Al*Bh, fp32 acc.
// Block 128x64, 8 warps. 2x 18 KB tile buffers (one sync per k-step); the
// 32 KB fp32 epilogue stage aliases them (all tile reads done before reuse).
__global__ __launch_bounds__(256) void k_gemm_bf3(
        const __nv_bfloat16* __restrict__ Ah, const __nv_bfloat16* __restrict__ Al,
        const __nv_bfloat16* __restrict__ Bh, const __nv_bfloat16* __restrict__ Bl,
        const float* __restrict__ bias, float* __restrict__ Out,
        int n, int m, int Kp) {
    __shared__ __align__(16) unsigned char sbuf[2 * 18432];
    float* stage = reinterpret_cast<float*>(sbuf);

    const int tid = threadIdx.x;
    const int wid = tid >> 5;
    const int wr  = wid & 3;
    const int wc  = wid >> 2;
    const int rb  = blockIdx.y * 128, cb = blockIdx.x * 64;

    const int ar  = tid >> 1;              // A tile row 0..127
    const int ak  = (tid & 1) * 8;         // k offset 0 / 8
    const int brr = tid >> 2;              // B tile row 0..63
    const int bk  = (tid & 3) * 4;         // k offset 0,4,8,12
    const size_t aoff = (size_t)min(rb + ar, n - 1) * Kp + ak;
    const size_t boff = (size_t)min(cb + brr, m - 1) * Kp + bk;
    const int aS = ar * 48 + ak * 2;       // byte offsets in a tile buffer
    const int bS = brr * 48 + bk * 2;
    const int nt = Kp >> 4;

    wmma::fragment<wmma::accumulator, 16, 16, 16, float> acc[2][2];
#pragma unroll
    for (int i = 0; i < 2; i++)
#pragma unroll
        for (int j = 0; j < 2; j++) wmma::fill_fragment(acc[i][j], 0.f);

    // tile 0 -> buffer 0
    uint4 rah = *(const uint4*)(Ah + aoff);
    uint4 ral = *(const uint4*)(Al + aoff);
    uint2 rbh = *(const uint2*)(Bh + boff);
    uint2 rbl = *(const uint2*)(Bl + boff);
    *(uint4*)(sbuf + aS)         = rah;
    *(uint4*)(sbuf + 6144 + aS)  = ral;
    *(uint2*)(sbuf + 12288 + bS) = rbh;
    *(uint2*)(sbuf + 15360 + bS) = rbl;
    __syncthreads();

    for (int it = 0; it < nt; ++it) {
        if (it + 1 < nt) {
            size_t ko = (size_t)(it + 1) * 16;
            rah = *(const uint4*)(Ah + aoff + ko);
            ral = *(const uint4*)(Al + aoff + ko);
            rbh = *(const uint2*)(Bh + boff + ko);
            rbl = *(const uint2*)(Bl + boff + ko);
        }
        unsigned char* bc = sbuf + (it & 1) * 18432;
        wmma::fragment<wmma::matrix_a, 16, 16, 16, __nv_bfloat16, wmma::row_major> fah[2], fal[2];
        wmma::fragment<wmma::matrix_b, 16, 16, 16, __nv_bfloat16, wmma::col_major> fbh[2], fbl[2];
#pragma unroll
        for (int i = 0; i < 2; i++) {
            wmma::load_matrix_sync(fah[i], (const __nv_bfloat16*)(bc + (wr * 32 + 16 * i) * 48), 24);
            wmma::load_matrix_sync(fal[i], (const __nv_bfloat16*)(bc + 6144 + (wr * 32 + 16 * i) * 48), 24);
        }
#pragma unroll
        for (int j = 0; j < 2; j++) {
            wmma::load_matrix_sync(fbh[j], (const __nv_bfloat16*)(bc + 12288 + (wc * 32 + 16 * j) * 48), 24);
            wmma::load_matrix_sync(fbl[j], (const __nv_bfloat16*)(bc + 15360 + (wc * 32 + 16 * j) * 48), 24);
        }
#pragma unroll
        for (int i = 0; i < 2; i++)
#pragma unroll
            for (int j = 0; j < 2; j++) {
                wmma::mma_sync(acc[i][j], fah[i], fbh[j], acc[i][j]);
                wmma::mma_sync(acc[i][j], fah[i], fbl[j], acc[i][j]);
                wmma::mma_sync(acc[i][j], fal[i], fbh[j], acc[i][j]);
            }
        if (it + 1 < nt) {
            unsigned char* bn = sbuf + ((it + 1) & 1) * 18432;
            *(uint4*)(bn + aS)         = rah;
            *(uint4*)(bn + 6144 + aS)  = ral;
            *(uint2*)(bn + 12288 + bS) = rbh;
            *(uint2*)(bn + 15360 + bS) = rbl;
        }
        __syncthreads();
    }

#pragma unroll
    for (int i = 0; i < 2; i++)
#pragma unroll
        for (int j = 0; j < 2; j++)
            wmma::store_matrix_sync(&stage[(wr * 32 + 16 * i) * 64 + wc * 32 + 16 * j],
                                    acc[i][j], 64, wmma::mem_row_major);
    __syncthreads();

    for (int s = tid; s < 128 * 16; s += 256) {
        int rr = s >> 4, c4 = (s & 15) * 4;
        int gr = rb + rr, gc = cb + c4;
        if (gr < n && gc < m) {
            float4 v = *(const float4*)&stage[rr * 64 + c4];
            if (bias) { v.x += bias[gc]; v.y += bias[gc+1]; v.z += bias[gc+2]; v.w += bias[gc+3]; }
            *(float4*)&Out[(size_t)gr * m + gc] = v;
        }
    }
}

// ---- weighted scatter-add; optional fold of 1/(sm[dst]+eps) into the weight -
__global__ void k_wagg(const int* __restrict__ srcIdx, const int* __restrict__ dstIdx,
                       const float* __restrict__ w, const float* __restrict__ smv,
                       const float* __restrict__ X,
                       int ss, float* out, int os, int ofs, int D, int ne) {
    int e    = (int)((blockIdx.x * (long long)blockDim.x + threadIdx.x) >> 5);
    int lane = threadIdx.x & 31;
    if (e >= ne) return;
    int dst = dstIdx[e];
    float wt = w[e];
    if (smv) wt = wt / (smv[dst] + 1e-16f);
    const float4* src = reinterpret_cast<const float4*>(X + (size_t)srcIdx[e] * ss);
    float* dstp = out + (size_t)dst * os + ofs;
    int D4 = D >> 2;
    for (int c = lane; c < D4; c += 32) {
        float4 v = src[c];
        red4(dstp + c * 4, wt * v.x, wt * v.y, wt * v.z, wt * v.w);
    }
}

// ---------------- highway combine (float4) -----------------------------------
__global__ void k_highway4(const float4* __restrict__ xin, const float4* __restrict__ x2,
                           const float4* __restrict__ gate, float4* out, long long n4, int relu2) {
    long long i = blockIdx.x * (long long)blockDim.x + threadIdx.x;
    if (i >= n4) return;
    float4 gv = gate[i], bv = x2[i], av = xin[i], o;
    float g;
    g = 1.f / (1.f + expf(-gv.x)); o.x = g * (relu2 ? fmaxf(bv.x, 0.f) : bv.x) + (1.f - g) * av.x;
    g = 1.f / (1.f + expf(-gv.y)); o.y = g * (relu2 ? fmaxf(bv.y, 0.f) : bv.y) + (1.f - g) * av.y;
    g = 1.f / (1.f + expf(-gv.z)); o.z = g * (relu2 ? fmaxf(bv.z, 0.f) : bv.z) + (1.f - g) * av.z;
    g = 1.f / (1.f + expf(-gv.w)); o.w = g * (relu2 ? fmaxf(bv.w, 0.f) : bv.w) + (1.f - g) * av.w;
    out[i] = o;
}

// highway (relu2=1) + emit split-bf16 of the result (row layout DD -> KP pad).
// Padding cols [300,304) stay zero from the earlier k_split pass over x_e.
__global__ void k_hwsplit(const float* __restrict__ xin, const float* __restrict__ x2,
                          const float* __restrict__ gate, float* __restrict__ out,
                          __nv_bfloat16* __restrict__ hi, __nv_bfloat16* __restrict__ lo) {
    long long i = blockIdx.x * (long long)blockDim.x + threadIdx.x;
    const int rw = DD / 4;                 // 75
    if (i >= (long long)NN * rw) return;
    int r = (int)(i / rw), c = (int)(i % rw) * 4;
    size_t o = (size_t)r * DD + c;
    float4 gv = *(const float4*)(gate + o);
    float4 bv = *(const float4*)(x2 + o);
    float4 av = *(const float4*)(xin + o);
    float4 ov;
    float g;
    g = 1.f / (1.f + expf(-gv.x)); ov.x = g * fmaxf(bv.x, 0.f) + (1.f - g) * av.x;
    g = 1.f / (1.f + expf(-gv.y)); ov.y = g * fmaxf(bv.y, 0.f) + (1.f - g) * av.y;
    g = 1.f / (1.f + expf(-gv.z)); ov.z = g * fmaxf(bv.z, 0.f) + (1.f - g) * av.z;
    g = 1.f / (1.f + expf(-gv.w)); ov.w = g * fmaxf(bv.w, 0.f) + (1.f - g) * av.w;
    *(float4*)(out + o) = ov;
    __nv_bfloat16 h[4], l[4];
    split4(ov, h, l);
    *(uint2*)(hi + (size_t)r * KP + c) = *(uint2*)h;
    *(uint2*)(lo + (size_t)r * KP + c) = *(uint2*)l;
}

// ---------------- segment softmax primitives ---------------------------------
__global__ void k_maxval(const float* __restrict__ val, const int* __restrict__ seg,
                         int* mx, int ne) {
    int e = blockIdx.x * blockDim.x + threadIdx.x;
    if (e < ne) atomicMax(&mx[seg[e]], encf(val[e]));
}
__global__ void k_expval(const float* __restrict__ vin, float* pout,
                         const int* __restrict__ seg, const int* __restrict__ mx,
                         float* sm, int ne) {
    int e = blockIdx.x * blockDim.x + threadIdx.x;
    if (e >= ne) return;
    float p = expf(vin[e] - decf(mx[seg[e]]));
    pout[e] = p;
    atomicAdd(&sm[seg[e]], p);
}
__global__ void k_div(float* p, const int* __restrict__ seg,
                      const float* __restrict__ sm, int ne) {
    int e = blockIdx.x * blockDim.x + threadIdx.x;
    if (e < ne) p[e] = p[e] / (sm[seg[e]] + 1e-16f);
}
__global__ void k_add(const float* a, const float* b, float* o, int ne) {
    int e = blockIdx.x * blockDim.x + threadIdx.x;
    if (e < ne) o[e] = a[e] + b[e];
}

__global__ void k_score(const float* __restrict__ pa, const int* __restrict__ ia,
                        const float* __restrict__ pb, const int* __restrict__ ib,
                        const float* __restrict__ pc, const int* __restrict__ ic,
                        const int* __restrict__ seg, float* out, int* mx, int ne) {
    int e = blockIdx.x * blockDim.x + threadIdx.x;
    if (e >= ne) return;
    float v = pa[ia[e]] + pb[ib[e]];
    if (pc) v += pc[ic[e]];
    v = v >= 0.f ? v : 0.01f * v;
    out[e] = v;
    atomicMax(&mx[seg[e]], encf(v));
}

// ---------------- relu / output prep -----------------------------------------
__global__ void k_relu(float* p, long long n) {
    long long i = blockIdx.x * (long long)blockDim.x + threadIdx.x;
    if (i < n) p[i] = fmaxf(p[i], 0.f);
}
__global__ void k_prep_out(float* out, const float* __restrict__ x) {
    long long i = blockIdx.x * (long long)blockDim.x + threadIdx.x;
    long long n = (long long)NN * 800;
    if (i >= n) return;
    int r = (int)(i / 800), c = (int)(i % 800);
    out[i] = (c < DD) ? x[(size_t)r * DD + c] : 0.f;
}
__global__ void k_relu_str(float* out, int rows, int rstride, int ofs, int D) {
    long long i = blockIdx.x * (long long)blockDim.x + threadIdx.x;
    long long n = (long long)rows * D;
    if (i >= n) return;
    int r = (int)(i / D), c = (int)(i % D);
    size_t p = (size_t)r * rstride + ofs + c;
    out[p] = fmaxf(out[p], 0.f);
}

// ---------------- per-row dot products (warp per row, float4) ----------------
__global__ void k_dot2(const float* __restrict__ X, int stride,
                       const float* __restrict__ a, const float* __restrict__ b,
                       float* outA, float* outB, int n, int D) {
    int w    = (int)((blockIdx.x * (long long)blockDim.x + threadIdx.x) >> 5);
    int lane = threadIdx.x & 31;
    if (w >= n) return;
    const float4* row = (const float4*)(X + (size_t)w * stride);
    const float4* a4 = (const float4*)a;
    const float4* b4 = (const float4*)b;
    float sa = 0.f, sb = 0.f;
    int D4 = D >> 2;
    for (int c = lane; c < D4; c += 32) {
        float4 x = row[c];
        float4 va = a4[c];
        sa += x.x * va.x + x.y * va.y + x.z * va.z + x.w * va.w;
        if (b) {
            float4 vb = b4[c];
            sb += x.x * vb.x + x.y * vb.y + x.z * vb.z + x.w * vb.w;
        }
    }
#pragma unroll
    for (int o = 16; o; o >>= 1) {
        sa += __shfl_down_sync(0xffffffffu, sa, o);
        if (b) sb += __shfl_down_sync(0xffffffffu, sb, o);
    }
    if (lane == 0) { outA[w] = sa; if (b) outB[w] = sb; }
}

__global__ void k_projR2(const float* __restrict__ relA, const float* __restrict__ relB,
                         const float* __restrict__ ar, float* out) {
    int w    = (int)((blockIdx.x * (long long)blockDim.x + threadIdx.x) >> 5);
    int lane = threadIdx.x & 31;
    if (w >= 2 * RRR) return;
    int r = w < RRR ? w : w - RRR;
    float s = 0.f;
    for (int c = lane; c < RH; c += 32)
        s += relA[(size_t)r * RH + c] * ar[c] + relB[(size_t)r * RH + c] * ar[RH + c];
#pragma unroll
    for (int o = 16; o; o >>= 1) s += __shfl_down_sync(0xffffffffu, s, o);
    if (lane == 0) out[w] = s;
}

// ---------------- host orchestration -----------------------------------------
static inline int divup(long long a, int b) { return (int)((a + b - 1) / b); }

extern "C" void kernel_launch(void* const* d_in, const int* in_sizes, int n_in,
                              void* d_out, int out_size) {
    const float* x_e      = (const float*)d_in[0];
    const float* merge_v  = (const float*)d_in[1];
    const float* tri_v    = (const float*)d_in[2];
    const float* gcn1_w   = (const float*)d_in[3];
    const float* hw1_w    = (const float*)d_in[4];
    const float* hw1_b    = (const float*)d_in[5];
    const float* gcn2_w   = (const float*)d_in[6];
    const float* hw2_w    = (const float*)d_in[7];
    const float* hw2_b    = (const float*)d_in[8];
    const float* rel_out1 = (const float*)d_in[9];
    const float* rel_tri1 = (const float*)d_in[10];
    const float* hwr_w    = (const float*)d_in[11];
    const float* hwr_b    = (const float*)d_in[12];
    const float* gat_ai   = (const float*)d_in[13];
    const float* gat_aj   = (const float*)d_in[14];
    const float* gat_ar   = (const float*)d_in[15];
    const float* g2e_ah   = (const float*)d_in[16];
    const float* g2e_at   = (const float*)d_in[17];
    const float* g2e_ar   = (const float*)d_in[18];
    const int*   ei       = (const int*)d_in[19];
    const int*   rel      = (const int*)d_in[20];
    const int*   eia      = (const int*)d_in[21];
    const int*   rel_all  = (const int*)d_in[22];
    const int*   lgm      = (const int*)d_in[23];
    const int*   lgt      = (const int*)d_in[24];
    float*       out      = (float*)d_out;

    float *px, *pt, *pagg, *pdeg, *pdinv, *penorm, *ppA, *ppB, *psm, *pew;
    float *pvi, *pvj, *pv2, *pal, *prsm, *prelA, *prelB, *prgate, *pxr, *pR2, *pR3;
    int *pmx, *prmx;
    __nv_bfloat16 *pAh, *pAl, *pBh, *pBl;
    cudaGetSymbolAddress((void**)&px, g_x);       cudaGetSymbolAddress((void**)&pt, g_t);
    cudaGetSymbolAddress((void**)&pagg, g_agg);   cudaGetSymbolAddress((void**)&pdeg, g_deg);
    cudaGetSymbolAddress((void**)&pdinv, g_dinv); cudaGetSymbolAddress((void**)&penorm, g_enorm);
    cudaGetSymbolAddress((void**)&ppA, g_pA);     cudaGetSymbolAddress((void**)&ppB, g_pB);
    cudaGetSymbolAddress((void**)&pmx, g_mx);     cudaGetSymbolAddress((void**)&psm, g_sm);
    cudaGetSymbolAddress((void**)&pew, g_ew);
    cudaGetSymbolAddress((void**)&pvi, g_vi);     cudaGetSymbolAddress((void**)&pvj, g_vj);
    cudaGetSymbolAddress((void**)&pv2, g_v2);     cudaGetSymbolAddress((void**)&pal, g_al);
    cudaGetSymbolAddress((void**)&prmx, g_rmx);   cudaGetSymbolAddress((void**)&prsm, g_rsm);
    cudaGetSymbolAddress((void**)&prelA, g_relA); cudaGetSymbolAddress((void**)&prelB, g_relB);
    cudaGetSymbolAddress((void**)&prgate, g_rgate); cudaGetSymbolAddress((void**)&pxr, g_xr);
    cudaGetSymbolAddress((void**)&pR2, g_projR2); cudaGetSymbolAddress((void**)&pR3, g_projR3);
    cudaGetSymbolAddress((void**)&pAh, g_Ah);     cudaGetSymbolAddress((void**)&pAl, g_Al);
    cudaGetSymbolAddress((void**)&pBh, g_Bh);     cudaGetSymbolAddress((void**)&pBl, g_Bl);

    const int* eia_j = eia;
    const int* eia_i = eia + EA;
    const int* ei_h  = ei;
    const int* ei_t  = ei + EE;

    dim3 gemmGbig(divup(DD, 64), divup(NN, 128));
    dim3 gemmGrel(divup(RH, 64), divup(RRR, 128));
    const long long splitBig4 = (long long)NN * (KP / 4);
    const long long splitW4   = (long long)DD * (KP / 4);
    const long long splitAr4  = (long long)RRR * (KPR / 4);
    const long long splitWr4  = (long long)RH * (KPR / 4);

    // ---------- degrees & per-edge gcn norm ----------
    k_zero<<<divup(NN, TPB), TPB>>>(pdeg, NN);
    k_deg<<<divup(EA, TPB), TPB>>>(eia_i, pdeg, EA);
    k_dinv<<<divup(NN, TPB), TPB>>>(pdeg, pdinv, NN);
    k_enorm<<<divup(EA, TPB), TPB>>>(eia_j, eia_i, pdinv, penorm, EA);

    const long long ND = (long long)NN * DD;
    const long long ND4 = ND / 4;
    const int aggBlocks = divup((long long)EA * 32, TPB);

    // ---------- GCN layer 1 + highway (emits layer-2 split) ----------
    k_split<<<divup(splitBig4, TPB), TPB>>>(x_e, pAh, pAl, NN, DD, KP);
    k_split<<<divup(splitW4, TPB), TPB>>>(gcn1_w, pBh, pBl, DD, DD, KP);
    k_gemm_bf3<<<gemmGbig, 256>>>(pAh, pAl, pBh, pBl, nullptr, pt, NN, DD, KP);
    k_zero<<<divup(ND, TPB), TPB>>>(pagg, ND);
    k_wagg<<<aggBlocks, TPB>>>(eia_j, eia_i, penorm, nullptr, pt, DD, pagg, DD, 0, DD, EA);
    k_split<<<divup(splitW4, TPB), TPB>>>(hw1_w, pBh, pBl, DD, DD, KP);
    k_gemm_bf3<<<gemmGbig, 256>>>(pAh, pAl, pBh, pBl, hw1_b, pt, NN, DD, KP);
    k_hwsplit<<<divup(ND4, TPB), TPB>>>(x_e, pagg, pt, px, pAh, pAl);

    // ---------- GCN layer 2 + highway ----------
    k_split<<<divup(splitW4, TPB), TPB>>>(gcn2_w, pBh, pBl, DD, DD, KP);
    k_gemm_bf3<<<gemmGbig, 256>>>(pAh, pAl, pBh, pBl, nullptr, pt, NN, DD, KP);
    k_zero<<<divup(ND, TPB), TPB>>>(pagg, ND);
    k_wagg<<<aggBlocks, TPB>>>(eia_j, eia_i, penorm, nullptr, pt, DD, pagg, DD, 0, DD, EA);
    k_split<<<divup(splitW4, TPB), TPB>>>(hw2_w, pBh, pBl, DD, DD, KP);
    k_gemm_bf3<<<gemmGbig, 256>>>(pAh, pAl, pBh, pBl, hw2_b, pt, NN, DD, KP);
    k_highway4<<<divup(ND4, TPB), TPB>>>((const float4*)px, (const float4*)pagg,
                                         (const float4*)pt, (float4*)px, ND4, 1);

    // ---------- l_gat (merge and triangular) ----------
    const float* lg_x[2]   = { rel_out1, rel_tri1 };
    const int*   lg_ei[2]  = { lgm, lgt };
    const float* lg_val[2] = { merge_v, tri_v };
    float*       lg_out[2] = { prelA, prelB };
    for (int q = 0; q < 2; q++) {
        const int* lj = lg_ei[q];
        const int* li = lg_ei[q] + LG;
        const float* val = lg_val[q];
        // vi = softmax over i
        k_initseg<<<divup(RRR, TPB), TPB>>>(prmx, prsm, RRR);
        k_maxval<<<divup(LG, TPB), TPB>>>(val, li, prmx, LG);
        k_expval<<<divup(LG, TPB), TPB>>>(val, pvi, li, prmx, prsm, LG);
        k_div  <<<divup(LG, TPB), TPB>>>(pvi, li, prsm, LG);
        // vj = softmax over j
        k_initseg<<<divup(RRR, TPB), TPB>>>(prmx, prsm, RRR);
        k_maxval<<<divup(LG, TPB), TPB>>>(val, lj, prmx, LG);
        k_expval<<<divup(LG, TPB), TPB>>>(val, pvj, lj, prmx, prsm, LG);
        k_div  <<<divup(LG, TPB), TPB>>>(pvj, lj, prsm, LG);
        // alpha = softmax(vi+vj) over j (seg != dst -> keep explicit div)
        k_add  <<<divup(LG, TPB), TPB>>>(pvi, pvj, pv2, LG);
        k_initseg<<<divup(RRR, TPB), TPB>>>(prmx, prsm, RRR);
        k_maxval<<<divup(LG, TPB), TPB>>>(pv2, lj, prmx, LG);
        k_expval<<<divup(LG, TPB), TPB>>>(pv2, pal, lj, prmx, prsm, LG);
        k_div  <<<divup(LG, TPB), TPB>>>(pal, lj, prsm, LG);
        // out[i] = relu(sum alpha * x[j])
        k_zero <<<divup((long long)RRR * RH, TPB), TPB>>>(lg_out[q], (long long)RRR * RH);
        k_wagg <<<divup((long long)LG * 32, TPB), TPB>>>(lj, li, pal, nullptr, lg_x[q], RH,
                                                         lg_out[q], RH, 0, RH, LG);
        k_relu <<<divup((long long)RRR * RH, TPB), TPB>>>(lg_out[q], (long long)RRR * RH);
    }

    // ---------- x_r = highway(rel_merge, rel_tri) ----------
    k_split<<<divup(splitAr4, TPB), TPB>>>(prelA, pAh, pAl, RRR, RH, KPR);
    k_split<<<divup(splitWr4, TPB), TPB>>>(hwr_w, pBh, pBl, RH, RH, KPR);
    k_gemm_bf3<<<gemmGrel, 256>>>(pAh, pAl, pBh, pBl, hwr_b, prgate, RRR, RH, KPR);
    k_highway4<<<divup((long long)RRR * RH / 4, TPB), TPB>>>(
        (const float4*)prelA, (const float4*)prelB, (const float4*)prgate,
        (float4*)pxr, (long long)RRR * RH / 4, 0);

    // ---------- entity GAT ----------
    k_dot2<<<divup((long long)NN * 32, TPB), TPB>>>(px, DD, gat_ai, gat_aj, ppA, ppB, NN, DD);
    k_projR2<<<divup((long long)2 * RRR * 32, TPB), TPB>>>(prelA, prelB, gat_ar, pR2);
    k_initseg<<<divup(NN, TPB), TPB>>>(pmx, psm, NN);
    k_score<<<divup(EA, TPB), TPB>>>(ppA, eia_i, ppB, eia_j, pR2, rel_all, eia_i, pew, pmx, EA);
    k_expval<<<divup(EA, TPB), TPB>>>(pew, pew, eia_i, pmx, psm, EA);
    // prep d_out (x into 0..299, zeros into 300..799), folded-div aggregate, relu
    k_prep_out<<<divup((long long)NN * 800, TPB), TPB>>>(out, px);
    k_wagg <<<aggBlocks, TPB>>>(eia_j, eia_i, pew, psm, px, DD, out, 800, 300, DD, EA);
    k_relu_str<<<divup((long long)NN * 300, TPB), TPB>>>(out, NN, 800, 300, 300);

    // ---------- relation -> entity GAT ----------
    k_dot2<<<divup((long long)NN * 32, TPB), TPB>>>(out, 800, g2e_ah, g2e_at, ppA, ppB, NN, 600);
    k_dot2<<<divup((long long)RRR * 32, TPB), TPB>>>(pxr, RH, g2e_ar, nullptr, pR3, nullptr, RRR, RH);

    // a1 over h -> cols 600..699 (div folded into scatter; seg == dst)
    k_initseg<<<divup(NN, TPB), TPB>>>(pmx, psm, NN);
    k_score<<<divup(EE, TPB), TPB>>>(ppA, ei_h, pR3, rel, nullptr, nullptr, ei_h, pew, pmx, EE);
    k_expval<<<divup(EE, TPB), TPB>>>(pew, pew, ei_h, pmx, psm, EE);
    k_wagg <<<divup((long long)EE * 32, TPB), TPB>>>(rel, ei_h, pew, psm, pxr, RH, out, 800, 600, RH, EE);

    // a2 over t -> cols 700..799
    k_initseg<<<divup(NN, TPB), TPB>>>(pmx, psm, NN);
    k_score<<<divup(EE, TPB), TPB>>>(ppB, ei_t, pR3, rel, nullptr, nullptr, ei_t, pew, pmx, EE);
    k_expval<<<divup(EE, TPB), TPB>>>(pew, pew, ei_t, pmx, psm, EE);
    k_wagg <<<divup((long long)EE * 32, TPB), TPB>>>(rel, ei_t, pew, psm, pxr, RH, out, 800, 700, RH, EE);

    (void)in_sizes; (void)n_in; (void)out_size;
}

// round 17
// speedup vs baseline: 2.3117x; 1.3201x over previous
#include <cuda_runtime.h>
#include <cuda_bf16.h>
#include <mma.h>
#include <math.h>

using namespace nvcuda;

// Problem constants (fixed by the dataset)
#define NN   100000   // entities
#define DD   300      // e_hidden
#define EE   400000   // triples (KG1)
#define EA   800000   // symmetric all-edge count (2*EH)
#define RRR  2000     // relations
#define RH   100      // r_hidden
#define LG   60000    // line-graph edges
#define KP   304      // padded K for big GEMMs
#define KPR  112      // padded K for relation GEMM

static const int TPB = 256;

// ---------------- device scratch (static globals; no allocation) -------------
__device__ float g_x   [(size_t)NN*DD];
__device__ float g_t   [(size_t)NN*DD];
__device__ float g_agg [(size_t)NN*DD];
__device__ float g_deg [NN];
__device__ float g_dinv[NN];
__device__ float g_enorm[EA];
__device__ float g_pA  [NN];
__device__ float g_pB  [NN];
__device__ int   g_mx  [NN];
__device__ float g_sm  [NN];
__device__ float g_ew  [EA];
__device__ float g_vi  [LG];
__device__ float g_vj  [LG];
__device__ float g_v2  [LG];
__device__ float g_al  [LG];
__device__ int   g_rmx [RRR];
__device__ float g_rsm [RRR];
__device__ float g_relA[RRR*RH];
__device__ float g_relB[RRR*RH];
__device__ float g_rgate[RRR*RH];
__device__ float g_xr  [RRR*RH];
__device__ float g_projR2[2*RRR];
__device__ float g_projR3[RRR];
__device__ __nv_bfloat16 g_Ah[(size_t)NN*KP];
__device__ __nv_bfloat16 g_Al[(size_t)NN*KP];
__device__ __nv_bfloat16 g_Bh[(size_t)DD*KP];
__device__ __nv_bfloat16 g_Bl[(size_t)DD*KP];
// CSR over the EA all-edge list keyed by dst (eia_i); reused by 3 aggregations
__device__ int g_off [NN + 1];
__device__ int g_cur [NN];
__device__ int g_perm[EA];
__device__ int g_bsum[512];

// ---------------- helpers ----------------------------------------------------
__device__ __forceinline__ int encf(float f) {
    int i = __float_as_int(f);
    return i >= 0 ? i : (i ^ 0x7fffffff);
}
__device__ __forceinline__ float decf(int i) {
    return __int_as_float(i >= 0 ? i : (i ^ 0x7fffffff));
}
__device__ __forceinline__ void red4(float* p, float a, float b, float c, float d) {
    asm volatile("red.global.add.v4.f32 [%0], {%1, %2, %3, %4};"
                 :: "l"(p), "f"(a), "f"(b), "f"(c), "f"(d) : "memory");
}
__device__ __forceinline__ void split4(float4 v, __nv_bfloat16* h, __nv_bfloat16* l) {
    h[0] = __float2bfloat16(v.x); l[0] = __float2bfloat16(v.x - __bfloat162float(h[0]));
    h[1] = __float2bfloat16(v.y); l[1] = __float2bfloat16(v.y - __bfloat162float(h[1]));
    h[2] = __float2bfloat16(v.z); l[2] = __float2bfloat16(v.z - __bfloat162float(h[2]));
    h[3] = __float2bfloat16(v.w); l[3] = __float2bfloat16(v.w - __bfloat162float(h[3]));
}

// ---------------- elementwise / init -----------------------------------------
__global__ void k_zero(float* p, long long n) {
    long long i = blockIdx.x * (long long)blockDim.x + threadIdx.x;
    if (i < n) p[i] = 0.f;
}
__global__ void k_initseg(int* mx, float* sm, int n) {
    int i = blockIdx.x * blockDim.x + threadIdx.x;
    if (i < n) { mx[i] = 0x80000000; sm[i] = 0.f; }
}

// ------- split fp32 -> (hi, lo) bf16, zero-padded to Kp (float4 path) --------
__global__ void k_split(const float* __restrict__ in, __nv_bfloat16* __restrict__ hi,
                        __nv_bfloat16* __restrict__ lo, int n, int K, int Kp) {
    long long i = blockIdx.x * (long long)blockDim.x + threadIdx.x;
    int kp4 = Kp >> 2;
    if (i >= (long long)n * kp4) return;
    int r = (int)(i / kp4), c = (int)(i % kp4) * 4;
    float4 v = make_float4(0.f, 0.f, 0.f, 0.f);
    if (c + 3 < K) v = *(const float4*)(in + (size_t)r * K + c);
    __nv_bfloat16 h[4], l[4];
    split4(v, h, l);
    *(uint2*)(hi + (size_t)r * Kp + c) = *(uint2*)h;
    *(uint2*)(lo + (size_t)r * Kp + c) = *(uint2*)l;
}

// ---------------- degree / norm ----------------------------------------------
__global__ void k_deg(const int* __restrict__ dst, float* deg, int ne) {
    int e = blockIdx.x * blockDim.x + threadIdx.x;
    if (e < ne) atomicAdd(&deg[dst[e]], 1.f);
}
__global__ void k_dinv(const float* __restrict__ deg, float* dinv, int n) {
    int i = blockIdx.x * blockDim.x + threadIdx.x;
    if (i < n) { float d = deg[i]; dinv[i] = d > 0.f ? rsqrtf(d) : 0.f; }
}
__global__ void k_enorm(const int* __restrict__ js, const int* __restrict__ is,
                        const float* __restrict__ dinv, float* en, int ne) {
    int e = blockIdx.x * blockDim.x + threadIdx.x;
    if (e < ne) en[e] = dinv[js[e]] * dinv[is[e]];
}

// ---------------- CSR build (dst-keyed) ---------------------------------------
__global__ void k_scan1(const float* __restrict__ deg, int* off, int* bsum, int n) {
    __shared__ int s[256];
    int i = blockIdx.x * 256 + threadIdx.x;
    int v = (i < n) ? (int)deg[i] : 0;
    s[threadIdx.x] = v;
    __syncthreads();
    for (int d = 1; d < 256; d <<= 1) {
        int t = (threadIdx.x >= d) ? s[threadIdx.x - d] : 0;
        __syncthreads();
        s[threadIdx.x] += t;
        __syncthreads();
    }
    if (i < n) off[i] = s[threadIdx.x] - v;            // block-local exclusive
    if (threadIdx.x == 255) bsum[blockIdx.x] = s[255]; // block total
}
__global__ void k_scan2(int* bsum, int nb) {           // single block, 512 thr
    __shared__ int s[512];
    int v = (threadIdx.x < nb) ? bsum[threadIdx.x] : 0;
    s[threadIdx.x] = v;
    __syncthreads();
    for (int d = 1; d < 512; d <<= 1) {
        int t = (threadIdx.x >= d) ? s[threadIdx.x - d] : 0;
        __syncthreads();
        s[threadIdx.x] += t;
        __syncthreads();
    }
    if (threadIdx.x < nb) bsum[threadIdx.x] = s[threadIdx.x] - v;  // exclusive
}
__global__ void k_scan3(int* off, const int* __restrict__ bsum, int* cur, int n, int ne) {
    int i = blockIdx.x * 256 + threadIdx.x;
    if (i < n) { int o = off[i] + bsum[i >> 8]; off[i] = o; cur[i] = o; }
    if (i == 0) off[n] = ne;
}
__global__ void k_perm(const int* __restrict__ dst, int* cur, int* perm, int ne) {
    int e = blockIdx.x * blockDim.x + threadIdx.x;
    if (e < ne) { int p = atomicAdd(&cur[dst[e]], 1); perm[p] = e; }
}

// ---- CSR gather: out[node, ofs:ofs+D] = (relu?)( scale * sum_e w[e]*X[src[e]] )
// warp per node; edge ids broadcast via shfl; plain (non-atomic) store.
__global__ void k_gather(const int* __restrict__ off, const int* __restrict__ perm,
                         const int* __restrict__ srcIdx, const float* __restrict__ w,
                         const float* __restrict__ smv, const float* __restrict__ X,
                         int ss, float* out, int os, int ofs, int D, int nNodes, int relu) {
    int node = (int)((blockIdx.x * (long long)blockDim.x + threadIdx.x) >> 5);
    int lane = threadIdx.x & 31;
    if (node >= nNodes) return;
    int o0 = off[node], o1 = off[node + 1];
    float acc[10];
#pragma unroll
    for (int k = 0; k < 10; k++) acc[k] = 0.f;
    for (int base = o0; base < o1; base += 32) {
        int idx = base + lane;
        int eid = (idx < o1) ? perm[idx] : 0;
        float wv = (idx < o1) ? w[eid] : 0.f;
        int   sv = (idx < o1) ? srcIdx[eid] : 0;
        int cnt = min(32, o1 - base);
        for (int t = 0; t < cnt; t++) {
            float wt = __shfl_sync(0xffffffffu, wv, t);
            int   sr = __shfl_sync(0xffffffffu, sv, t);
            const float* row = X + (size_t)sr * ss;
#pragma unroll
            for (int k = 0; k < 10; k++) {
                int c = lane + 32 * k;
                if (c < D) acc[k] += wt * row[c];
            }
        }
    }
    float scale = smv ? 1.f / (smv[node] + 1e-16f) : 1.f;
    float* op = out + (size_t)node * os + ofs;
#pragma unroll
    for (int k = 0; k < 10; k++) {
        int c = lane + 32 * k;
        if (c < D) {
            float v = acc[k] * scale;
            if (relu) v = fmaxf(v, 0.f);
            op[c] = v;
        }
    }
}

// ---- GEMM (tensor core, split-bf16 3-MMA, double-buffered smem) -------------
__global__ __launch_bounds__(256) void k_gemm_bf3(
        const __nv_bfloat16* __restrict__ Ah, const __nv_bfloat16* __restrict__ Al,
        const __nv_bfloat16* __restrict__ Bh, const __nv_bfloat16* __restrict__ Bl,
        const float* __restrict__ bias, float* __restrict__ Out,
        int n, int m, int Kp) {
    __shared__ __align__(16) unsigned char sbuf[2 * 18432];
    float* stage = reinterpret_cast<float*>(sbuf);

    const int tid = threadIdx.x;
    const int wid = tid >> 5;
    const int wr  = wid & 3;
    const int wc  = wid >> 2;
    const int rb  = blockIdx.y * 128, cb = blockIdx.x * 64;

    const int ar  = tid >> 1;
    const int ak  = (tid & 1) * 8;
    const int brr = tid >> 2;
    const int bk  = (tid & 3) * 4;
    const size_t aoff = (size_t)min(rb + ar, n - 1) * Kp + ak;
    const size_t boff = (size_t)min(cb + brr, m - 1) * Kp + bk;
    const int aS = ar * 48 + ak * 2;
    const int bS = brr * 48 + bk * 2;
    const int nt = Kp >> 4;

    wmma::fragment<wmma::accumulator, 16, 16, 16, float> acc[2][2];
#pragma unroll
    for (int i = 0; i < 2; i++)
#pragma unroll
        for (int j = 0; j < 2; j++) wmma::fill_fragment(acc[i][j], 0.f);

    uint4 rah = *(const uint4*)(Ah + aoff);
    uint4 ral = *(const uint4*)(Al + aoff);
    uint2 rbh = *(const uint2*)(Bh + boff);
    uint2 rbl = *(const uint2*)(Bl + boff);
    *(uint4*)(sbuf + aS)         = rah;
    *(uint4*)(sbuf + 6144 + aS)  = ral;
    *(uint2*)(sbuf + 12288 + bS) = rbh;
    *(uint2*)(sbuf + 15360 + bS) = rbl;
    __syncthreads();

    for (int it = 0; it < nt; ++it) {
        if (it + 1 < nt) {
            size_t ko = (size_t)(it + 1) * 16;
            rah = *(const uint4*)(Ah + aoff + ko);
            ral = *(const uint4*)(Al + aoff + ko);
            rbh = *(const uint2*)(Bh + boff + ko);
            rbl = *(const uint2*)(Bl + boff + ko);
        }
        unsigned char* bc = sbuf + (it & 1) * 18432;
        wmma::fragment<wmma::matrix_a, 16, 16, 16, __nv_bfloat16, wmma::row_major> fah[2], fal[2];
        wmma::fragment<wmma::matrix_b, 16, 16, 16, __nv_bfloat16, wmma::col_major> fbh[2], fbl[2];
#pragma unroll
        for (int i = 0; i < 2; i++) {
            wmma::load_matrix_sync(fah[i], (const __nv_bfloat16*)(bc + (wr * 32 + 16 * i) * 48), 24);
            wmma::load_matrix_sync(fal[i], (const __nv_bfloat16*)(bc + 6144 + (wr * 32 + 16 * i) * 48), 24);
        }
#pragma unroll
        for (int j = 0; j < 2; j++) {
            wmma::load_matrix_sync(fbh[j], (const __nv_bfloat16*)(bc + 12288 + (wc * 32 + 16 * j) * 48), 24);
            wmma::load_matrix_sync(fbl[j], (const __nv_bfloat16*)(bc + 15360 + (wc * 32 + 16 * j) * 48), 24);
        }
#pragma unroll
        for (int i = 0; i < 2; i++)
#pragma unroll
            for (int j = 0; j < 2; j++) {
                wmma::mma_sync(acc[i][j], fah[i], fbh[j], acc[i][j]);
                wmma::mma_sync(acc[i][j], fah[i], fbl[j], acc[i][j]);
                wmma::mma_sync(acc[i][j], fal[i], fbh[j], acc[i][j]);
            }
        if (it + 1 < nt) {
            unsigned char* bn = sbuf + ((it + 1) & 1) * 18432;
            *(uint4*)(bn + aS)         = rah;
            *(uint4*)(bn + 6144 + aS)  = ral;
            *(uint2*)(bn + 12288 + bS) = rbh;
            *(uint2*)(bn + 15360 + bS) = rbl;
        }
        __syncthreads();
    }

#pragma unroll
    for (int i = 0; i < 2; i++)
#pragma unroll
        for (int j = 0; j < 2; j++)
            wmma::store_matrix_sync(&stage[(wr * 32 + 16 * i) * 64 + wc * 32 + 16 * j],
                                    acc[i][j], 64, wmma::mem_row_major);
    __syncthreads();

    for (int s = tid; s < 128 * 16; s += 256) {
        int rr = s >> 4, c4 = (s & 15) * 4;
        int gr = rb + rr, gc = cb + c4;
        if (gr < n && gc < m) {
            float4 v = *(const float4*)&stage[rr * 64 + c4];
            if (bias) { v.x += bias[gc]; v.y += bias[gc+1]; v.z += bias[gc+2]; v.w += bias[gc+3]; }
            *(float4*)&Out[(size_t)gr * m + gc] = v;
        }
    }
}

// ---- weighted scatter-add (atomic); optional fold of 1/(sm[dst]+eps) --------
__global__ void k_wagg(const int* __restrict__ srcIdx, const int* __restrict__ dstIdx,
                       const float* __restrict__ w, const float* __restrict__ smv,
                       const float* __restrict__ X,
                       int ss, float* out, int os, int ofs, int D, int ne) {
    int e    = (int)((blockIdx.x * (long long)blockDim.x + threadIdx.x) >> 5);
    int lane = threadIdx.x & 31;
    if (e >= ne) return;
    int dst = dstIdx[e];
    float wt = w[e];
    if (smv) wt = wt / (smv[dst] + 1e-16f);
    const float4* src = reinterpret_cast<const float4*>(X + (size_t)srcIdx[e] * ss);
    float* dstp = out + (size_t)dst * os + ofs;
    int D4 = D >> 2;
    for (int c = lane; c < D4; c += 32) {
        float4 v = src[c];
        red4(dstp + c * 4, wt * v.x, wt * v.y, wt * v.z, wt * v.w);
    }
}

// ---------------- highway combine (float4) -----------------------------------
__global__ void k_highway4(const float4* __restrict__ xin, const float4* __restrict__ x2,
                           const float4* __restrict__ gate, float4* out, long long n4, int relu2) {
    long long i = blockIdx.x * (long long)blockDim.x + threadIdx.x;
    if (i >= n4) return;
    float4 gv = gate[i], bv = x2[i], av = xin[i], o;
    float g;
    g = 1.f / (1.f + expf(-gv.x)); o.x = g * (relu2 ? fmaxf(bv.x, 0.f) : bv.x) + (1.f - g) * av.x;
    g = 1.f / (1.f + expf(-gv.y)); o.y = g * (relu2 ? fmaxf(bv.y, 0.f) : bv.y) + (1.f - g) * av.y;
    g = 1.f / (1.f + expf(-gv.z)); o.z = g * (relu2 ? fmaxf(bv.z, 0.f) : bv.z) + (1.f - g) * av.z;
    g = 1.f / (1.f + expf(-gv.w)); o.w = g * (relu2 ? fmaxf(bv.w, 0.f) : bv.w) + (1.f - g) * av.w;
    out[i] = o;
}

// highway (relu2=1) + emit split-bf16 of the result (pad cols stay zero)
__global__ void k_hwsplit(const float* __restrict__ xin, const float* __restrict__ x2,
                          const float* __restrict__ gate, float* __restrict__ out,
                          __nv_bfloat16* __restrict__ hi, __nv_bfloat16* __restrict__ lo) {
    long long i = blockIdx.x * (long long)blockDim.x + threadIdx.x;
    const int rw = DD / 4;
    if (i >= (long long)NN * rw) return;
    int r = (int)(i / rw), c = (int)(i % rw) * 4;
    size_t o = (size_t)r * DD + c;
    float4 gv = *(const float4*)(gate + o);
    float4 bv = *(const float4*)(x2 + o);
    float4 av = *(const float4*)(xin + o);
    float4 ov;
    float g;
    g = 1.f / (1.f + expf(-gv.x)); ov.x = g * fmaxf(bv.x, 0.f) + (1.f - g) * av.x;
    g = 1.f / (1.f + expf(-gv.y)); ov.y = g * fmaxf(bv.y, 0.f) + (1.f - g) * av.y;
    g = 1.f / (1.f + expf(-gv.z)); ov.z = g * fmaxf(bv.z, 0.f) + (1.f - g) * av.z;
    g = 1.f / (1.f + expf(-gv.w)); ov.w = g * fmaxf(bv.w, 0.f) + (1.f - g) * av.w;
    *(float4*)(out + o) = ov;
    __nv_bfloat16 h[4], l[4];
    split4(ov, h, l);
    *(uint2*)(hi + (size_t)r * KP + c) = *(uint2*)h;
    *(uint2*)(lo + (size_t)r * KP + c) = *(uint2*)l;
}

// ---------------- segment softmax primitives ---------------------------------
__global__ void k_maxval(const float* __restrict__ val, const int* __restrict__ seg,
                         int* mx, int ne) {
    int e = blockIdx.x * blockDim.x + threadIdx.x;
    if (e < ne) atomicMax(&mx[seg[e]], encf(val[e]));
}
__global__ void k_expval(const float* __restrict__ vin, float* pout,
                         const int* __restrict__ seg, const int* __restrict__ mx,
                         float* sm, int ne) {
    int e = blockIdx.x * blockDim.x + threadIdx.x;
    if (e >= ne) return;
    float p = expf(vin[e] - decf(mx[seg[e]]));
    pout[e] = p;
    atomicAdd(&sm[seg[e]], p);
}
__global__ void k_div(float* p, const int* __restrict__ seg,
                      const float* __restrict__ sm, int ne) {
    int e = blockIdx.x * blockDim.x + threadIdx.x;
    if (e < ne) p[e] = p[e] / (sm[seg[e]] + 1e-16f);
}
__global__ void k_add(const float* a, const float* b, float* o, int ne) {
    int e = blockIdx.x * blockDim.x + threadIdx.x;
    if (e < ne) o[e] = a[e] + b[e];
}

__global__ void k_score(const float* __restrict__ pa, const int* __restrict__ ia,
                        const float* __restrict__ pb, const int* __restrict__ ib,
                        const float* __restrict__ pc, const int* __restrict__ ic,
                        const int* __restrict__ seg, float* out, int* mx, int ne) {
    int e = blockIdx.x * blockDim.x + threadIdx.x;
    if (e >= ne) return;
    float v = pa[ia[e]] + pb[ib[e]];
    if (pc) v += pc[ic[e]];
    v = v >= 0.f ? v : 0.01f * v;
    out[e] = v;
    atomicMax(&mx[seg[e]], encf(v));
}

// ---------------- relu / output prep -----------------------------------------
__global__ void k_relu(float* p, long long n) {
    long long i = blockIdx.x * (long long)blockDim.x + threadIdx.x;
    if (i < n) p[i] = fmaxf(p[i], 0.f);
}
// d_out prep: cols 0..299 <- x, 600..799 <- 0; cols 300..599 skipped
// (fully overwritten by the GAT CSR gather that follows).
__global__ void k_prep_out(float* out, const float* __restrict__ x) {
    long long i = blockIdx.x * (long long)blockDim.x + threadIdx.x;
    long long n = (long long)NN * 800;
    if (i >= n) return;
    int r = (int)(i / 800), c = (int)(i % 800);
    if (c < DD)       out[i] = x[(size_t)r * DD + c];
    else if (c >= 600) out[i] = 0.f;
}

// ---------------- per-row dot products (warp per row, float4) ----------------
__global__ void k_dot2(const float* __restrict__ X, int stride,
                       const float* __restrict__ a, const float* __restrict__ b,
                       float* outA, float* outB, int n, int D) {
    int w    = (int)((blockIdx.x * (long long)blockDim.x + threadIdx.x) >> 5);
    int lane = threadIdx.x & 31;
    if (w >= n) return;
    const float4* row = (const float4*)(X + (size_t)w * stride);
    const float4* a4 = (const float4*)a;
    const float4* b4 = (const float4*)b;
    float sa = 0.f, sb = 0.f;
    int D4 = D >> 2;
    for (int c = lane; c < D4; c += 32) {
        float4 x = row[c];
        float4 va = a4[c];
        sa += x.x * va.x + x.y * va.y + x.z * va.z + x.w * va.w;
        if (b) {
            float4 vb = b4[c];
            sb += x.x * vb.x + x.y * vb.y + x.z * vb.z + x.w * vb.w;
        }
    }
#pragma unroll
    for (int o = 16; o; o >>= 1) {
        sa += __shfl_down_sync(0xffffffffu, sa, o);
        if (b) sb += __shfl_down_sync(0xffffffffu, sb, o);
    }
    if (lane == 0) { outA[w] = sa; if (b) outB[w] = sb; }
}

__global__ void k_projR2(const float* __restrict__ relA, const float* __restrict__ relB,
                         const float* __restrict__ ar, float* out) {
    int w    = (int)((blockIdx.x * (long long)blockDim.x + threadIdx.x) >> 5);
    int lane = threadIdx.x & 31;
    if (w >= 2 * RRR) return;
    int r = w < RRR ? w : w - RRR;
    float s = 0.f;
    for (int c = lane; c < RH; c += 32)
        s += relA[(size_t)r * RH + c] * ar[c] + relB[(size_t)r * RH + c] * ar[RH + c];
#pragma unroll
    for (int o = 16; o; o >>= 1) s += __shfl_down_sync(0xffffffffu, s, o);
    if (lane == 0) out[w] = s;
}

// ---------------- host orchestration -----------------------------------------
static inline int divup(long long a, int b) { return (int)((a + b - 1) / b); }

extern "C" void kernel_launch(void* const* d_in, const int* in_sizes, int n_in,
                              void* d_out, int out_size) {
    const float* x_e      = (const float*)d_in[0];
    const float* merge_v  = (const float*)d_in[1];
    const float* tri_v    = (const float*)d_in[2];
    const float* gcn1_w   = (const float*)d_in[3];
    const float* hw1_w    = (const float*)d_in[4];
    const float* hw1_b    = (const float*)d_in[5];
    const float* gcn2_w   = (const float*)d_in[6];
    const float* hw2_w    = (const float*)d_in[7];
    const float* hw2_b    = (const float*)d_in[8];
    const float* rel_out1 = (const float*)d_in[9];
    const float* rel_tri1 = (const float*)d_in[10];
    const float* hwr_w    = (const float*)d_in[11];
    const float* hwr_b    = (const float*)d_in[12];
    const float* gat_ai   = (const float*)d_in[13];
    const float* gat_aj   = (const float*)d_in[14];
    const float* gat_ar   = (const float*)d_in[15];
    const float* g2e_ah   = (const float*)d_in[16];
    const float* g2e_at   = (const float*)d_in[17];
    const float* g2e_ar   = (const float*)d_in[18];
    const int*   ei       = (const int*)d_in[19];
    const int*   rel      = (const int*)d_in[20];
    const int*   eia      = (const int*)d_in[21];
    const int*   rel_all  = (const int*)d_in[22];
    const int*   lgm      = (const int*)d_in[23];
    const int*   lgt      = (const int*)d_in[24];
    float*       out      = (float*)d_out;

    float *px, *pt, *pagg, *pdeg, *pdinv, *penorm, *ppA, *ppB, *psm, *pew;
    float *pvi, *pvj, *pv2, *pal, *prsm, *prelA, *prelB, *prgate, *pxr, *pR2, *pR3;
    int *pmx, *prmx, *poff, *pcur, *pperm, *pbsum;
    __nv_bfloat16 *pAh, *pAl, *pBh, *pBl;
    cudaGetSymbolAddress((void**)&px, g_x);       cudaGetSymbolAddress((void**)&pt, g_t);
    cudaGetSymbolAddress((void**)&pagg, g_agg);   cudaGetSymbolAddress((void**)&pdeg, g_deg);
    cudaGetSymbolAddress((void**)&pdinv, g_dinv); cudaGetSymbolAddress((void**)&penorm, g_enorm);
    cudaGetSymbolAddress((void**)&ppA, g_pA);     cudaGetSymbolAddress((void**)&ppB, g_pB);
    cudaGetSymbolAddress((void**)&pmx, g_mx);     cudaGetSymbolAddress((void**)&psm, g_sm);
    cudaGetSymbolAddress((void**)&pew, g_ew);
    cudaGetSymbolAddress((void**)&pvi, g_vi);     cudaGetSymbolAddress((void**)&pvj, g_vj);
    cudaGetSymbolAddress((void**)&pv2, g_v2);     cudaGetSymbolAddress((void**)&pal, g_al);
    cudaGetSymbolAddress((void**)&prmx, g_rmx);   cudaGetSymbolAddress((void**)&prsm, g_rsm);
    cudaGetSymbolAddress((void**)&prelA, g_relA); cudaGetSymbolAddress((void**)&prelB, g_relB);
    cudaGetSymbolAddress((void**)&prgate, g_rgate); cudaGetSymbolAddress((void**)&pxr, g_xr);
    cudaGetSymbolAddress((void**)&pR2, g_projR2); cudaGetSymbolAddress((void**)&pR3, g_projR3);
    cudaGetSymbolAddress((void**)&pAh, g_Ah);     cudaGetSymbolAddress((void**)&pAl, g_Al);
    cudaGetSymbolAddress((void**)&pBh, g_Bh);     cudaGetSymbolAddress((void**)&pBl, g_Bl);
    cudaGetSymbolAddress((void**)&poff, g_off);   cudaGetSymbolAddress((void**)&pcur, g_cur);
    cudaGetSymbolAddress((void**)&pperm, g_perm); cudaGetSymbolAddress((void**)&pbsum, g_bsum);

    const int* eia_j = eia;
    const int* eia_i = eia + EA;
    const int* ei_h  = ei;
    const int* ei_t  = ei + EE;

    dim3 gemmGbig(divup(DD, 64), divup(NN, 128));
    dim3 gemmGrel(divup(RH, 64), divup(RRR, 128));
    const long long splitBig4 = (long long)NN * (KP / 4);
    const long long splitW4   = (long long)DD * (KP / 4);
    const long long splitAr4  = (long long)RRR * (KPR / 4);
    const long long splitWr4  = (long long)RH * (KPR / 4);

    const long long ND = (long long)NN * DD;
    const long long ND4 = ND / 4;
    const int gatherBlocks = divup((long long)NN * 32, TPB);
    const int scanBlocks = divup(NN, 256);

    // ---------- degrees, gcn norm, and EA CSR (dst = eia_i) ----------
    k_zero<<<divup(NN, TPB), TPB>>>(pdeg, NN);
    k_deg<<<divup(EA, TPB), TPB>>>(eia_i, pdeg, EA);
    k_dinv<<<divup(NN, TPB), TPB>>>(pdeg, pdinv, NN);
    k_enorm<<<divup(EA, TPB), TPB>>>(eia_j, eia_i, pdinv, penorm, EA);
    k_scan1<<<scanBlocks, 256>>>(pdeg, poff, pbsum, NN);
    k_scan2<<<1, 512>>>(pbsum, scanBlocks);
    k_scan3<<<scanBlocks, 256>>>(poff, pbsum, pcur, NN, EA);
    k_perm<<<divup(EA, TPB), TPB>>>(eia_i, pcur, pperm, EA);

    // ---------- GCN layer 1 + highway (emits layer-2 split) ----------
    k_split<<<divup(splitBig4, TPB), TPB>>>(x_e, pAh, pAl, NN, DD, KP);
    k_split<<<divup(splitW4, TPB), TPB>>>(gcn1_w, pBh, pBl, DD, DD, KP);
    k_gemm_bf3<<<gemmGbig, 256>>>(pAh, pAl, pBh, pBl, nullptr, pt, NN, DD, KP);
    k_gather<<<gatherBlocks, TPB>>>(poff, pperm, eia_j, penorm, nullptr, pt, DD,
                                    pagg, DD, 0, DD, NN, 0);
    k_split<<<divup(splitW4, TPB), TPB>>>(hw1_w, pBh, pBl, DD, DD, KP);
    k_gemm_bf3<<<gemmGbig, 256>>>(pAh, pAl, pBh, pBl, hw1_b, pt, NN, DD, KP);
    k_hwsplit<<<divup(ND4, TPB), TPB>>>(x_e, pagg, pt, px, pAh, pAl);

    // ---------- GCN layer 2 + highway ----------
    k_split<<<divup(splitW4, TPB), TPB>>>(gcn2_w, pBh, pBl, DD, DD, KP);
    k_gemm_bf3<<<gemmGbig, 256>>>(pAh, pAl, pBh, pBl, nullptr, pt, NN, DD, KP);
    k_gather<<<gatherBlocks, TPB>>>(poff, pperm, eia_j, penorm, nullptr, pt, DD,
                                    pagg, DD, 0, DD, NN, 0);
    k_split<<<divup(splitW4, TPB), TPB>>>(hw2_w, pBh, pBl, DD, DD, KP);
    k_gemm_bf3<<<gemmGbig, 256>>>(pAh, pAl, pBh, pBl, hw2_b, pt, NN, DD, KP);
    k_highway4<<<divup(ND4, TPB), TPB>>>((const float4*)px, (const float4*)pagg,
                                         (const float4*)pt, (float4*)px, ND4, 1);

    // ---------- l_gat (merge and triangular) ----------
    const float* lg_x[2]   = { rel_out1, rel_tri1 };
    const int*   lg_ei[2]  = { lgm, lgt };
    const float* lg_val[2] = { merge_v, tri_v };
    float*       lg_out[2] = { prelA, prelB };
    for (int q = 0; q < 2; q++) {
        const int* lj = lg_ei[q];
        const int* li = lg_ei[q] + LG;
        const float* val = lg_val[q];
        k_initseg<<<divup(RRR, TPB), TPB>>>(prmx, prsm, RRR);
        k_maxval<<<divup(LG, TPB), TPB>>>(val, li, prmx, LG);
        k_expval<<<divup(LG, TPB), TPB>>>(val, pvi, li, prmx, prsm, LG);
        k_div  <<<divup(LG, TPB), TPB>>>(pvi, li, prsm, LG);
        k_initseg<<<divup(RRR, TPB), TPB>>>(prmx, prsm, RRR);
        k_maxval<<<divup(LG, TPB), TPB>>>(val, lj, prmx, LG);
        k_expval<<<divup(LG, TPB), TPB>>>(val, pvj, lj, prmx, prsm, LG);
        k_div  <<<divup(LG, TPB), TPB>>>(pvj, lj, prsm, LG);
        k_add  <<<divup(LG, TPB), TPB>>>(pvi, pvj, pv2, LG);
        k_initseg<<<divup(RRR, TPB), TPB>>>(prmx, prsm, RRR);
        k_maxval<<<divup(LG, TPB), TPB>>>(pv2, lj, prmx, LG);
        k_expval<<<divup(LG, TPB), TPB>>>(pv2, pal, lj, prmx, prsm, LG);
        k_div  <<<divup(LG, TPB), TPB>>>(pal, lj, prsm, LG);
        k_zero <<<divup((long long)RRR * RH, TPB), TPB>>>(lg_out[q], (long long)RRR * RH);
        k_wagg <<<divup((long long)LG * 32, TPB), TPB>>>(lj, li, pal, nullptr, lg_x[q], RH,
                                                         lg_out[q], RH, 0, RH, LG);
        k_relu <<<divup((long long)RRR * RH, TPB), TPB>>>(lg_out[q], (long long)RRR * RH);
    }

    // ---------- x_r = highway(rel_merge, rel_tri) ----------
    k_split<<<divup(splitAr4, TPB), TPB>>>(prelA, pAh, pAl, RRR, RH, KPR);
    k_split<<<divup(splitWr4, TPB), TPB>>>(hwr_w, pBh, pBl, RH, RH, KPR);
    k_gemm_bf3<<<gemmGrel, 256>>>(pAh, pAl, pBh, pBl, hwr_b, prgate, RRR, RH, KPR);
    k_highway4<<<divup((long long)RRR * RH / 4, TPB), TPB>>>(
        (const float4*)prelA, (const float4*)prelB, (const float4*)prgate,
        (float4*)pxr, (long long)RRR * RH / 4, 0);

    // ---------- entity GAT (CSR gather, relu + div folded) ----------
    k_dot2<<<divup((long long)NN * 32, TPB), TPB>>>(px, DD, gat_ai, gat_aj, ppA, ppB, NN, DD);
    k_projR2<<<divup((long long)2 * RRR * 32, TPB), TPB>>>(prelA, prelB, gat_ar, pR2);
    k_initseg<<<divup(NN, TPB), TPB>>>(pmx, psm, NN);
    k_score<<<divup(EA, TPB), TPB>>>(ppA, eia_i, ppB, eia_j, pR2, rel_all, eia_i, pew, pmx, EA);
    k_expval<<<divup(EA, TPB), TPB>>>(pew, pew, eia_i, pmx, psm, EA);
    k_prep_out<<<divup((long long)NN * 800, TPB), TPB>>>(out, px);
    k_gather<<<gatherBlocks, TPB>>>(poff, pperm, eia_j, pew, psm, px, DD,
                                    out, 800, 300, DD, NN, 1);

    // ---------- relation -> entity GAT (atomic, folded div) ----------
    k_dot2<<<divup((long long)NN * 32, TPB), TPB>>>(out, 800, g2e_ah, g2e_at, ppA, ppB, NN, 600);
    k_dot2<<<divup((long long)RRR * 32, TPB), TPB>>>(pxr, RH, g2e_ar, nullptr, pR3, nullptr, RRR, RH);

    k_initseg<<<divup(NN, TPB), TPB>>>(pmx, psm, NN);
    k_score<<<divup(EE, TPB), TPB>>>(ppA, ei_h, pR3, rel, nullptr, nullptr, ei_h, pew, pmx, EE);
    k_expval<<<divup(EE, TPB), TPB>>>(pew, pew, ei_h, pmx, psm, EE);
    k_wagg <<<divup((long long)EE * 32, TPB), TPB>>>(rel, ei_h, pew, psm, pxr, RH, out, 800, 600, RH, EE);

    k_initseg<<<divup(NN, TPB), TPB>>>(pmx, psm, NN);
    k_score<<<divup(EE, TPB), TPB>>>(ppB, ei_t, pR3, rel, nullptr, nullptr, ei_t, pew, pmx, EE);
    k_expval<<<divup(EE, TPB), TPB>>>(pew, pew, ei_t, pmx, psm, EE);
    k_wagg <<<divup((long long)EE * 32, TPB), TPB>>>(rel, ei_t, pew, psm, pxr, RH, out, 800, 700, RH, EE);

    (void)in_sizes; (void)n_in; (void)out_size;
}